// round 12
// baseline (speedup 1.0000x reference)
#include <cuda_runtime.h>
#include <cstdint>

// ---------------------------------------------------------------- constants
#define N_ROWS   65536
#define DIMV     128
#define KCODES   1024
#define RPB      128                  // rows per block (M)
#define CPC      64                   // codes per chunk (N)
#define NCH      (KCODES / CPC)       // 16
#define TPB      256
#define NBLOCKS  (N_ROWS / RPB)       // 512

// padded int8 row: 128 data + 16 pad = 144 B (9 x 16B granules, ldsm-clean)
#define ROWB8    144
#define XA_L     (RPB * ROWB8)        // 18432 per x limb
#define B_L      (CPC * ROWB8)        // 9216 per e limb
#define B_CH     (2 * B_L)            // 18432 per chunk (both limbs)
#define ET8      (KCODES * ROWB8)     // 147456 per e limb plane

// smem layout (total 82544 -> 2 blocks/SM easily)
#define SM_XA    0
#define SM_B     (2 * XA_L)                   // 36864 (double-buffered chunks)
#define SM_RE    (SM_B + 2 * B_CH)            // 73728
#define SM_RX    (SM_RE + KCODES * 4)         // 77824
#define SM_REDD  (SM_RX + RPB * 4)            // 78336
#define SM_REDI  (SM_REDD + RPB * 4 * 4)      // 80384
#define SM_LOSS  (SM_REDI + RPB * 4 * 4)      // 82432
#define SM_RED2  (SM_LOSS + 64)               // 82496
#define SM_FLAG  (SM_RED2 + 32)               // 82528
#define SMEM_TOTAL (SM_FLAG + 16)             // 82544

// fixed-point scales (powers of 2; cross terms share 2^-28)
#define S1R   16.0f                    // 1/s1, s1 = 2^-4
#define S1    0.0625f
#define S2R   2048.0f                  // 1/s2, s2 = 2^-11
#define T1R   131072.0f                // 1/t1, t1 = 2^-17
#define T1    (1.0f / 131072.0f)
#define T2R   16777216.0f              // 1/t2, t2 = 2^-24
#define CMAIN 4.76837158203125e-7f     // 2^-21 = s1*t1
#define CCROSS 3.725290298461914e-9f   // 2^-28 = s2*t1 = s1*t2

// ---------------------------------------------------------------- scratch
__device__ float        g_re[KCODES];
__device__ int          g_counts[KCODES];
__device__ double       g_loss;
__device__ unsigned int g_ticket;
// int8 codebook limbs: [2][1024][144]
__device__ __align__(16) unsigned char g_e8[2u * ET8];

// ---------------------------------------------------------------- helpers
__device__ __forceinline__ uint32_t smem_u32(const void* p) {
    uint32_t a;
    asm("{ .reg .u64 t; cvta.to.shared.u64 t, %1; cvt.u32.u64 %0, t; }"
        : "=r"(a) : "l"(p));
    return a;
}
static __device__ __forceinline__ void cp_async16(uint32_t dst, const void* src) {
    asm volatile("cp.async.cg.shared.global [%0], [%1], 16;\n" :: "r"(dst), "l"(src));
}
#define CP_COMMIT() asm volatile("cp.async.commit_group;\n" ::: "memory")
#define CP_WAIT1()  asm volatile("cp.async.wait_group 1;\n" ::: "memory")

#define LDSM4(r, addr) \
    asm volatile("ldmatrix.sync.aligned.m8n8.x4.shared.b16 {%0,%1,%2,%3}, [%4];" \
        : "=r"((r)[0]), "=r"((r)[1]), "=r"((r)[2]), "=r"((r)[3]) : "r"(addr))

#define MMAI8(c, a, b0, b1) \
    asm volatile("mma.sync.aligned.m16n8k32.row.col.s32.s8.s8.s32 " \
        "{%0,%1,%2,%3}, {%4,%5,%6,%7}, {%8,%9}, {%0,%1,%2,%3};" \
        : "+r"((c)[0]), "+r"((c)[1]), "+r"((c)[2]), "+r"((c)[3]) \
        : "r"((a)[0]), "r"((a)[1]), "r"((a)[2]), "r"((a)[3]), "r"(b0), "r"(b1))

// ordering: (dA,iA) < (dB,iB)  [strict, lowest index on ties]
static __device__ __forceinline__ bool lt(float dA, int iA, float dB, int iB) {
    return dA < dB || (dA == dB && iA < iB);
}
static __device__ __forceinline__ void ins2(float d, int i,
                                            float& bD, int& bI, float& sD, int& sI) {
    if (lt(d, i, bD, bI)) { sD = bD; sI = bI; bD = d; bI = i; }
    else if (lt(d, i, sD, sI)) { sD = d; sI = i; }
}

static __device__ __forceinline__ void quant2(float v, float inv1, float sc1,
                                              float inv2, int& q1, int& q2) {
    q1 = __float2int_rn(v * inv1);
    q1 = max(-127, min(127, q1));
    float r = __fmaf_rn((float)q1, -sc1, v);
    q2 = __float2int_rn(r * inv2);
    q2 = max(-127, min(127, q2));
}
static __device__ __forceinline__ uint32_t pack4(int a, int b, int c, int d) {
    return (uint32_t)(a & 255) | ((uint32_t)(b & 255) << 8)
         | ((uint32_t)(c & 255) << 16) | ((uint32_t)(d & 255) << 24);
}

// ---------------------------------------------------------------- prep
// 2 threads per code: ||e||^2 (fp32 squares, fp64 sum -> fp32) + int8 limbs.
__global__ void vq_prep(const float* __restrict__ emb) {
    int g = blockIdx.x * blockDim.x + threadIdx.x;   // 0..2047
    int k = g >> 1, half = g & 1;
    const float4* e4 = (const float4*)(emb + (size_t)k * DIMV + half * 64);
    double s = 0.0;
    uint32_t w1[16], w2[16];
#pragma unroll
    for (int i = 0; i < 16; ++i) {
        float4 v = e4[i];
        s += (double)__fmul_rn(v.x, v.x) + (double)__fmul_rn(v.y, v.y)
           + (double)__fmul_rn(v.z, v.z) + (double)__fmul_rn(v.w, v.w);
        int ax, bx, ay, by, az, bz, aw, bw;
        quant2(v.x, T1R, T1, T2R, ax, bx);
        quant2(v.y, T1R, T1, T2R, ay, by);
        quant2(v.z, T1R, T1, T2R, az, bz);
        quant2(v.w, T1R, T1, T2R, aw, bw);
        w1[i] = pack4(ax, ay, az, aw);
        w2[i] = pack4(bx, by, bz, bw);
    }
    {
        uint4* d1 = (uint4*)(g_e8 + (size_t)k * ROWB8 + half * 64);
        uint4* d2 = (uint4*)(g_e8 + ET8 + (size_t)k * ROWB8 + half * 64);
#pragma unroll
        for (int i = 0; i < 4; ++i) {
            d1[i] = make_uint4(w1[4*i], w1[4*i+1], w1[4*i+2], w1[4*i+3]);
            d2[i] = make_uint4(w2[4*i], w2[4*i+1], w2[4*i+2], w2[4*i+3]);
        }
    }
    s += __shfl_xor_sync(0xffffffffu, s, 1);
    if (!half) { g_re[k] = (float)s; g_counts[k] = 0; }
    if (g == 0) { g_loss = 0.0; g_ticket = 0u; }
}

// ---------------------------------------------------------------- main
__global__ __launch_bounds__(TPB, 2)
void vq_main(const float* __restrict__ x, const float* __restrict__ emb,
             float* __restrict__ out, int out_size) {
    extern __shared__ __align__(16) char sm[];
    float*  sRE   = (float*)(sm + SM_RE);
    float*  sRX   = (float*)(sm + SM_RX);
    float*  sRedD = (float*)(sm + SM_REDD);
    int*    sRedI = (int*)  (sm + SM_REDI);
    double* sLoss = (double*)(sm + SM_LOSS);
    float*  sRed2 = (float*)(sm + SM_RED2);
    unsigned int* sFlag = (unsigned int*)(sm + SM_FLAG);

    const uint32_t smb = smem_u32(sm);
    const int tid = threadIdx.x, wid = tid >> 5, l = tid & 31;
    const int wm = wid & 3, wn = wid >> 2;          // 4 x 2 warp grid
    const size_t row0 = (size_t)blockIdx.x * RPB;

    // ---- stage x int8 limbs + fp64 row norms ----
    {
        int row = tid >> 1, half = tid & 1;
        const float4* xr = (const float4*)(x + (row0 + row) * DIMV + half * 64);
        double s = 0.0;
        uint32_t w1[16], w2[16];
#pragma unroll
        for (int i = 0; i < 16; ++i) {
            float4 v = xr[i];
            s += (double)__fmul_rn(v.x, v.x) + (double)__fmul_rn(v.y, v.y)
               + (double)__fmul_rn(v.z, v.z) + (double)__fmul_rn(v.w, v.w);
            int ax, bx, ay, by, az, bz, aw, bw;
            quant2(v.x, S1R, S1, S2R, ax, bx);
            quant2(v.y, S1R, S1, S2R, ay, by);
            quant2(v.z, S1R, S1, S2R, az, bz);
            quant2(v.w, S1R, S1, S2R, aw, bw);
            w1[i] = pack4(ax, ay, az, aw);
            w2[i] = pack4(bx, by, bz, bw);
        }
        uint4* d1 = (uint4*)(sm + SM_XA + row * ROWB8 + half * 64);
        uint4* d2 = (uint4*)(sm + SM_XA + XA_L + row * ROWB8 + half * 64);
#pragma unroll
        for (int i = 0; i < 4; ++i) {
            d1[i] = make_uint4(w1[4*i], w1[4*i+1], w1[4*i+2], w1[4*i+3]);
            d2[i] = make_uint4(w2[4*i], w2[4*i+1], w2[4*i+2], w2[4*i+3]);
        }
        s += __shfl_xor_sync(0xffffffffu, s, 1);
        if (!half) sRX[row] = (float)s;
    }
    for (int i = tid; i < KCODES; i += TPB) sRE[i] = g_re[i];

    // ---- prefetch B chunks 0,1 (double-buffered) ----
    {
#pragma unroll
        for (int c = 0; c < 2; ++c) {
            uint32_t dst = smb + SM_B + c * B_CH;
            const unsigned char* src = g_e8 + (size_t)c * CPC * ROWB8;
            for (int i = tid; i < B_CH / 16; i += TPB) {
                int sp = i / (B_L / 16), r = i - sp * (B_L / 16);
                cp_async16(dst + i * 16, src + (size_t)sp * ET8 + r * 16);
            }
            CP_COMMIT();
        }
    }
    __syncthreads();   // staging of A/rx visible

    float rxv[4];
#pragma unroll
    for (int s = 0; s < 4; ++s) rxv[s] = sRX[wm * 32 + (l >> 2) + s * 8];

    uint32_t aAddr[2][2];
#pragma unroll
    for (int sp = 0; sp < 2; ++sp)
#pragma unroll
        for (int mi = 0; mi < 2; ++mi)
            aAddr[sp][mi] = smb + SM_XA + sp * XA_L
                          + (wm * 32 + mi * 16 + (l & 15)) * ROWB8 + ((l >> 4) & 1) * 16;
    uint32_t bOff[2][2];   // [limb][16-code group]
#pragma unroll
    for (int sp = 0; sp < 2; ++sp)
#pragma unroll
        for (int g = 0; g < 2; ++g)
            bOff[sp][g] = sp * B_L
                        + (wn * 32 + g * 16 + (l & 7) + ((l >> 4) & 1) * 8) * ROWB8
                        + ((l >> 3) & 1) * 16;

    float bestD[4], secD[4];
    int   bestI[4], secI[4];
#pragma unroll
    for (int s = 0; s < 4; ++s) {
        bestD[s] = secD[s] = 3.402823466e38f;
        bestI[s] = secI[s] = 0x7fffffff;
    }

#pragma unroll 1
    for (int c = 0; c < NCH; ++c) {
        CP_WAIT1();
        __syncthreads();                 // buf (c&1) ready for all
        uint32_t bB = smb + SM_B + (c & 1) * B_CH;

        int accM[2][4][4], accX[2][4][4];
#pragma unroll
        for (int mi = 0; mi < 2; ++mi)
#pragma unroll
            for (int ni = 0; ni < 4; ++ni)
#pragma unroll
                for (int q = 0; q < 4; ++q) { accM[mi][ni][q] = 0; accX[mi][ni][q] = 0; }

#pragma unroll
        for (int ks = 0; ks < 4; ++ks) {   // k32 per step, K=128
            uint32_t A1[2][4], A2[2][4], B1[2][4], B2[2][4];
#pragma unroll
            for (int mi = 0; mi < 2; ++mi) {
                LDSM4(A1[mi], aAddr[0][mi] + ks * 32);
                LDSM4(A2[mi], aAddr[1][mi] + ks * 32);
            }
#pragma unroll
            for (int g = 0; g < 2; ++g) LDSM4(B1[g], bB + bOff[0][g] + ks * 32);
            // main (a1,b1) and cross (a2,b1)
#pragma unroll
            for (int mi = 0; mi < 2; ++mi)
#pragma unroll
                for (int ni = 0; ni < 4; ++ni) {
                    int g = ni >> 1, h = (ni & 1) * 2;
                    MMAI8(accM[mi][ni], A1[mi], B1[g][h], B1[g][h + 1]);
                    MMAI8(accX[mi][ni], A2[mi], B1[g][h], B1[g][h + 1]);
                }
#pragma unroll
            for (int g = 0; g < 2; ++g) LDSM4(B2[g], bB + bOff[1][g] + ks * 32);
            // cross (a1,b2) — same scale as (a2,b1), shared accumulator
#pragma unroll
            for (int mi = 0; mi < 2; ++mi)
#pragma unroll
                for (int ni = 0; ni < 4; ++ni) {
                    int g = ni >> 1, h = (ni & 1) * 2;
                    MMAI8(accX[mi][ni], A1[mi], B2[g][h], B2[g][h + 1]);
                }
        }

        // epilogue: combine scales, reference-style distance + running top-2
        int cb = c * CPC + wn * 32;
#pragma unroll
        for (int mi = 0; mi < 2; ++mi) {
#pragma unroll
            for (int ni = 0; ni < 4; ++ni) {
                int code = cb + ni * 8 + 2 * (l & 3);
                float re0 = sRE[code], re1 = sRE[code + 1];
                int s0 = mi * 2, s1 = mi * 2 + 1;
                float m, d;
                m = __fmaf_rn(CMAIN, (float)accM[mi][ni][0], CCROSS * (float)accX[mi][ni][0]);
                d = __fadd_rn(__fadd_rn(rxv[s0], re0), __fmul_rn(m, -2.0f));
                ins2(d, code,     bestD[s0], bestI[s0], secD[s0], secI[s0]);
                m = __fmaf_rn(CMAIN, (float)accM[mi][ni][1], CCROSS * (float)accX[mi][ni][1]);
                d = __fadd_rn(__fadd_rn(rxv[s0], re1), __fmul_rn(m, -2.0f));
                ins2(d, code + 1, bestD[s0], bestI[s0], secD[s0], secI[s0]);
                m = __fmaf_rn(CMAIN, (float)accM[mi][ni][2], CCROSS * (float)accX[mi][ni][2]);
                d = __fadd_rn(__fadd_rn(rxv[s1], re0), __fmul_rn(m, -2.0f));
                ins2(d, code,     bestD[s1], bestI[s1], secD[s1], secI[s1]);
                m = __fmaf_rn(CMAIN, (float)accM[mi][ni][3], CCROSS * (float)accX[mi][ni][3]);
                d = __fadd_rn(__fadd_rn(rxv[s1], re1), __fmul_rn(m, -2.0f));
                ins2(d, code + 1, bestD[s1], bestI[s1], secD[s1], secI[s1]);
            }
        }
        __syncthreads();                 // readers done with buf (c&1)
        if (c + 2 < NCH) {               // prefetch chunk c+2 into freed buffer
            uint32_t dst = smb + SM_B + (c & 1) * B_CH;
            const unsigned char* src = g_e8 + (size_t)(c + 2) * CPC * ROWB8;
            for (int i = tid; i < B_CH / 16; i += TPB) {
                int sp = i / (B_L / 16), r = i - sp * (B_L / 16);
                cp_async16(dst + i * 16, src + (size_t)sp * ET8 + r * 16);
            }
            CP_COMMIT();
        }
    }

    // ---- top-2 merge across lanes (bfly over l&3) ----
#pragma unroll
    for (int s = 0; s < 4; ++s) {
#pragma unroll
        for (int m = 1; m <= 2; m <<= 1) {
            float obD = __shfl_xor_sync(0xffffffffu, bestD[s], m);
            int   obI = __shfl_xor_sync(0xffffffffu, bestI[s], m);
            float osD = __shfl_xor_sync(0xffffffffu, secD[s], m);
            int   osI = __shfl_xor_sync(0xffffffffu, secI[s], m);
            ins2(obD, obI, bestD[s], bestI[s], secD[s], secI[s]);
            ins2(osD, osI, bestD[s], bestI[s], secD[s], secI[s]);
        }
    }
    if ((l & 3) == 0) {
#pragma unroll
        for (int s = 0; s < 4; ++s) {
            int r = wm * 32 + (l >> 2) + s * 8;
            sRedD[(r * 2 + wn) * 2]     = bestD[s];
            sRedD[(r * 2 + wn) * 2 + 1] = secD[s];
            sRedI[(r * 2 + wn) * 2]     = bestI[s];
            sRedI[(r * 2 + wn) * 2 + 1] = secI[s];
        }
    }
    __syncthreads();

    // ---- per-row final: EXACT fp32 recheck of ALL 4 candidates ----
    if (tid < RPB) {
        const float4* xr = (const float4*)(x + (row0 + tid) * DIMV);
        float rx = sRX[tid];
        float bD = 3.402823466e38f;
        int   bi = 0x7fffffff;
#pragma unroll
        for (int t = 0; t < 4; ++t) {
            int cd = sRedI[tid * 4 + t];
            const float4* er = (const float4*)(emb + (size_t)cd * DIMV);
            float a0 = 0.f, a1 = 0.f, a2 = 0.f, a3 = 0.f;
#pragma unroll 8
            for (int j = 0; j < 32; ++j) {
                float4 xv = xr[j], ev = er[j];
                a0 = __fmaf_rn(xv.x, ev.x, a0);
                a1 = __fmaf_rn(xv.y, ev.y, a1);
                a2 = __fmaf_rn(xv.z, ev.z, a2);
                a3 = __fmaf_rn(xv.w, ev.w, a3);
            }
            float m = __fadd_rn(__fadd_rn(a0, a1), __fadd_rn(a2, a3));
            float d = __fadd_rn(__fadd_rn(rx, sRE[cd]), __fmul_rn(m, -2.0f));
            if (lt(d, cd, bD, bi)) { bD = d; bi = cd; }
        }
        sRedI[tid * 4] = bi;             // reuse as per-row best index
        atomicAdd(&g_counts[bi], 1);
    }
    __syncthreads();

    // ---- fused output: STE-rounded gather + fp64 loss partial ----
    double ls = 0.0;
    {
        const float4* xin4 = (const float4*)(x + row0 * DIMV);
        float4*       o4   = (float4*)(out + row0 * DIMV);
        const float4* e4   = (const float4*)emb;
        for (int i = tid; i < RPB * (DIMV / 4); i += TPB) {
            int rr  = i >> 5;
            int col = i & 31;
            float4 q  = e4[(size_t)sRedI[rr * 4] * 32 + col];
            float4 xv = xin4[i];
            float4 o;
            o.x = __fadd_rn(xv.x, __fadd_rn(q.x, -xv.x));
            o.y = __fadd_rn(xv.y, __fadd_rn(q.y, -xv.y));
            o.z = __fadd_rn(xv.z, __fadd_rn(q.z, -xv.z));
            o.w = __fadd_rn(xv.w, __fadd_rn(q.w, -xv.w));
            o4[i] = o;
            double dx = (double)q.x - xv.x, dy = (double)q.y - xv.y;
            double dz = (double)q.z - xv.z, dw = (double)q.w - xv.w;
            ls += dx * dx + dy * dy + dz * dz + dw * dw;
        }
    }
#pragma unroll
    for (int o = 16; o > 0; o >>= 1) ls += __shfl_down_sync(0xffffffffu, ls, o);
    if (l == 0) sLoss[wid] = ls;
    __syncthreads();
    if (tid == 0) {
        double t = 0.0;
#pragma unroll
        for (int i = 0; i < 8; ++i) t += sLoss[i];
        atomicAdd(&g_loss, t);
        __threadfence();
        unsigned int tk = atomicAdd(&g_ticket, 1u);
        sFlag[0] = (tk == (unsigned int)(NBLOCKS - 1)) ? 1u : 0u;
    }
    __syncthreads();

    // ---- fused finalize (last block only): perplexity + loss scalars ----
    if (sFlag[0]) {
        __threadfence();
        float acc = 0.f;
        for (int k = tid; k < KCODES; k += TPB) {
            float p = (float)__ldcg(&g_counts[k]) * (1.0f / (float)N_ROWS);
            acc += p * logf(p + 1e-10f);
        }
#pragma unroll
        for (int o = 16; o > 0; o >>= 1) acc += __shfl_down_sync(0xffffffffu, acc, o);
        if (l == 0) sRed2[wid] = acc;
        __syncthreads();
        if (tid == 0) {
            float s = 0.f;
#pragma unroll
            for (int i = 0; i < 8; ++i) s += sRed2[i];
            double lv = __ldcg(&g_loss);
            out[out_size - 2] = (float)(1.25 * (lv / (double)(N_ROWS * DIMV)));
            out[out_size - 1] = expf(-s);
        }
    }
}

// ----------------------------------------------------------------
extern "C" void kernel_launch(void* const* d_in, const int* in_sizes, int n_in,
                              void* d_out, int out_size) {
    const float* x   = (const float*)d_in[0];
    const float* emb = (const float*)d_in[1];
    float*       out = (float*)d_out;
    (void)in_sizes; (void)n_in;

    cudaFuncSetAttribute(vq_main, cudaFuncAttributeMaxDynamicSharedMemorySize,
                         SMEM_TOTAL);

    vq_prep<<<8, 256>>>(emb);
    vq_main<<<NBLOCKS, TPB, SMEM_TOTAL>>>(x, emb, out, out_size);
}

// round 13
// speedup vs baseline: 1.4302x; 1.4302x over previous
#include <cuda_runtime.h>
#include <cuda_bf16.h>
#include <cstdint>

// ---------------------------------------------------------------- constants
#define N_ROWS   65536
#define DIMV     128
#define KCODES   1024
#define RPB      128                  // rows per block (M)
#define CPC      64                   // codes per chunk (N)
#define NCH      (KCODES / CPC)       // 16
#define TPB      256
#define NBLOCKS  (N_ROWS / RPB)       // 512

// padded bf16 row: 136 elems = 272 B = 17 x 16B granules (conflict-free ldmatrix)
#define ROWB     272
#define XA_B     (RPB * ROWB)         // 34816 (single limb)
#define B_CH     (CPC * ROWB)         // 17408 per chunk (single limb)
#define ETB      (KCODES * ROWB)      // 278528

// smem layout (total 82544 -> 2 blocks/SM)
#define SM_XA    0
#define SM_B     XA_B                         // 34816 (double-buffered chunks)
#define SM_RE    (SM_B + 2 * B_CH)            // 69632
#define SM_RX    (SM_RE + KCODES * 4)         // 73728
#define SM_REDD  (SM_RX + RPB * 4)            // 74240
#define SM_REDI  (SM_REDD + RPB * 8 * 4)      // 78336
#define SM_LOSS  (SM_REDI + RPB * 8 * 4)      // 82432
#define SM_RED2  (SM_LOSS + 64)               // 82496
#define SM_FLAG  (SM_RED2 + 32)               // 82528
#define SMEM_TOTAL (SM_FLAG + 16)             // 82544

// ---------------------------------------------------------------- scratch
__device__ float        g_re[KCODES];
__device__ int          g_counts[KCODES];
__device__ double       g_loss;
__device__ unsigned int g_ticket;
// bf16 codebook (rounded), padded rows: [1024][136] bf16
__device__ __align__(16) unsigned char g_eT[ETB];

// ---------------------------------------------------------------- helpers
__device__ __forceinline__ uint32_t smem_u32(const void* p) {
    uint32_t a;
    asm("{ .reg .u64 t; cvta.to.shared.u64 t, %1; cvt.u32.u64 %0, t; }"
        : "=r"(a) : "l"(p));
    return a;
}
static __device__ __forceinline__ void cp_async16(uint32_t dst, const void* src) {
    asm volatile("cp.async.cg.shared.global [%0], [%1], 16;\n" :: "r"(dst), "l"(src));
}
#define CP_COMMIT() asm volatile("cp.async.commit_group;\n" ::: "memory")
#define CP_WAIT1()  asm volatile("cp.async.wait_group 1;\n" ::: "memory")
#define CP_WAIT0()  asm volatile("cp.async.wait_group 0;\n" ::: "memory")

#define LDSM4(r, addr) \
    asm volatile("ldmatrix.sync.aligned.m8n8.x4.shared.b16 {%0,%1,%2,%3}, [%4];" \
        : "=r"((r)[0]), "=r"((r)[1]), "=r"((r)[2]), "=r"((r)[3]) : "r"(addr))

#define MMA16816(c, a, b0, b1) \
    asm volatile("mma.sync.aligned.m16n8k16.row.col.f32.bf16.bf16.f32 " \
        "{%0,%1,%2,%3}, {%4,%5,%6,%7}, {%8,%9}, {%0,%1,%2,%3};" \
        : "+f"((c)[0]), "+f"((c)[1]), "+f"((c)[2]), "+f"((c)[3]) \
        : "r"((a)[0]), "r"((a)[1]), "r"((a)[2]), "r"((a)[3]), "r"(b0), "r"(b1))

// ordering: (dA,iA) < (dB,iB)  [strict, lowest index on ties]
static __device__ __forceinline__ bool lt(float dA, int iA, float dB, int iB) {
    return dA < dB || (dA == dB && iA < iB);
}
// insert candidate into a top-4 list (rank 0 best)
static __device__ __forceinline__ void ins4(float d, int i, float (&D)[4], int (&I)[4]) {
    if (!lt(d, i, D[3], I[3])) return;
    if (lt(d, i, D[1], I[1])) {
        D[3] = D[2]; I[3] = I[2];
        D[2] = D[1]; I[2] = I[1];
        if (lt(d, i, D[0], I[0])) { D[1] = D[0]; I[1] = I[0]; D[0] = d; I[0] = i; }
        else                      { D[1] = d;    I[1] = i; }
    } else {
        if (lt(d, i, D[2], I[2])) { D[3] = D[2]; I[3] = I[2]; D[2] = d; I[2] = i; }
        else                      { D[3] = d;    I[3] = i; }
    }
}

// ---------------------------------------------------------------- prep
// 2 threads per code: ||e||^2 (fp32 squares, fp64 sum -> fp32) + bf16 tile.
__global__ void vq_prep(const float* __restrict__ emb) {
    int g = blockIdx.x * blockDim.x + threadIdx.x;   // 0..2047
    int k = g >> 1, half = g & 1;
    const float4* e4 = (const float4*)(emb + (size_t)k * DIMV + half * 64);
    unsigned char* base = g_eT + (size_t)k * ROWB + half * 128;
    double s = 0.0;
#pragma unroll
    for (int i = 0; i < 16; ++i) {
        float4 v = e4[i];
        s += (double)__fmul_rn(v.x, v.x) + (double)__fmul_rn(v.y, v.y)
           + (double)__fmul_rn(v.z, v.z) + (double)__fmul_rn(v.w, v.w);
        *(__nv_bfloat162*)(base + i * 8)     =
            __halves2bfloat162(__float2bfloat16_rn(v.x), __float2bfloat16_rn(v.y));
        *(__nv_bfloat162*)(base + i * 8 + 4) =
            __halves2bfloat162(__float2bfloat16_rn(v.z), __float2bfloat16_rn(v.w));
    }
    s += __shfl_xor_sync(0xffffffffu, s, 1);
    if (!half) { g_re[k] = (float)s; g_counts[k] = 0; }
    if (g == 0) { g_loss = 0.0; g_ticket = 0u; }
}

// ---------------------------------------------------------------- main
__global__ __launch_bounds__(TPB, 2)
void vq_main(const float* __restrict__ x, const float* __restrict__ emb,
             float* __restrict__ out, int out_size) {
    extern __shared__ __align__(16) char sm[];
    float*  sRE   = (float*)(sm + SM_RE);
    float*  sRX   = (float*)(sm + SM_RX);
    float*  sRedD = (float*)(sm + SM_REDD);
    int*    sRedI = (int*)  (sm + SM_REDI);
    double* sLoss = (double*)(sm + SM_LOSS);
    float*  sRed2 = (float*)(sm + SM_RED2);
    unsigned int* sFlag = (unsigned int*)(sm + SM_FLAG);

    const uint32_t smb = smem_u32(sm);
    const int tid = threadIdx.x, wid = tid >> 5, l = tid & 31;
    const int wm = wid & 3, wn = wid >> 2;          // 4 x 2 warp grid
    const size_t row0 = (size_t)blockIdx.x * RPB;

    // ---- prefetch B chunks 0,1 (double-buffered) ----
#pragma unroll
    for (int c = 0; c < 2; ++c) {
        uint32_t dst = smb + SM_B + c * B_CH;
        const unsigned char* src = g_eT + (size_t)c * B_CH;
        for (int i = tid; i < B_CH / 16; i += TPB)
            cp_async16(dst + i * 16, src + i * 16);
        CP_COMMIT();
    }

    // ---- stage x (bf16, padded) + fp64 row norms ----
    {
        int row = tid >> 1, half = tid & 1;
        const float4* xr = (const float4*)(x + (row0 + row) * DIMV + half * 64);
        char* base = sm + SM_XA + row * ROWB + half * 128;
        double s = 0.0;
#pragma unroll
        for (int i = 0; i < 16; ++i) {
            float4 v = xr[i];
            s += (double)__fmul_rn(v.x, v.x) + (double)__fmul_rn(v.y, v.y)
               + (double)__fmul_rn(v.z, v.z) + (double)__fmul_rn(v.w, v.w);
            *(__nv_bfloat162*)(base + i * 8)     =
                __halves2bfloat162(__float2bfloat16_rn(v.x), __float2bfloat16_rn(v.y));
            *(__nv_bfloat162*)(base + i * 8 + 4) =
                __halves2bfloat162(__float2bfloat16_rn(v.z), __float2bfloat16_rn(v.w));
        }
        s += __shfl_xor_sync(0xffffffffu, s, 1);
        if (!half) sRX[row] = (float)s;
    }
    for (int i = tid; i < KCODES; i += TPB) sRE[i] = g_re[i];
    __syncthreads();   // staging of A/rx visible

    uint32_t aAddr[2];
#pragma unroll
    for (int mi = 0; mi < 2; ++mi)
        aAddr[mi] = smb + SM_XA
                  + (wm * 32 + mi * 16 + (l & 15)) * ROWB + ((l >> 4) & 1) * 16;
    uint32_t bOff[2];
#pragma unroll
    for (int g = 0; g < 2; ++g)
        bOff[g] = (wn * 32 + g * 16 + (l & 7) + ((l >> 4) & 1) * 8) * ROWB
                + ((l >> 3) & 1) * 16;

    // per-slot top-4 (4 row-slots per thread)
    float tD[4][4];
    int   tI[4][4];
#pragma unroll
    for (int s = 0; s < 4; ++s)
#pragma unroll
        for (int r = 0; r < 4; ++r) { tD[s][r] = 3.402823466e38f; tI[s][r] = 0x7fffffff; }

#pragma unroll 1
    for (int c = 0; c < NCH; ++c) {
        if (c + 1 < NCH) CP_WAIT1(); else CP_WAIT0();
        __syncthreads();                 // buf (c&1) ready for all
        uint32_t bB = smb + SM_B + (c & 1) * B_CH;

        float acc[2][4][4];
#pragma unroll
        for (int mi = 0; mi < 2; ++mi)
#pragma unroll
            for (int ni = 0; ni < 4; ++ni)
#pragma unroll
                for (int q = 0; q < 4; ++q) acc[mi][ni][q] = 0.f;

#pragma unroll
        for (int ks = 0; ks < 8; ++ks) {
            uint32_t A[2][4], B[2][4];
            LDSM4(A[0], aAddr[0] + ks * 32);
            LDSM4(A[1], aAddr[1] + ks * 32);
            LDSM4(B[0], bB + bOff[0] + ks * 32);
            LDSM4(B[1], bB + bOff[1] + ks * 32);
#pragma unroll
            for (int mi = 0; mi < 2; ++mi)
#pragma unroll
                for (int ni = 0; ni < 4; ++ni)
                    MMA16816(acc[mi][ni], A[mi],
                             B[ni >> 1][(ni & 1) * 2], B[ni >> 1][(ni & 1) * 2 + 1]);
        }

        // epilogue: selection metric s = re - 2*m (rx restored in recheck)
        int cb = c * CPC + wn * 32;
#pragma unroll
        for (int mi = 0; mi < 2; ++mi) {
#pragma unroll
            for (int ni = 0; ni < 4; ++ni) {
                int code = cb + ni * 8 + 2 * (l & 3);
                float re0 = sRE[code], re1 = sRE[code + 1];
                int s0 = mi * 2, s1 = mi * 2 + 1;
                float s;
                s = __fmaf_rn(acc[mi][ni][0], -2.0f, re0); ins4(s, code,     tD[s0], tI[s0]);
                s = __fmaf_rn(acc[mi][ni][1], -2.0f, re1); ins4(s, code + 1, tD[s0], tI[s0]);
                s = __fmaf_rn(acc[mi][ni][2], -2.0f, re0); ins4(s, code,     tD[s1], tI[s1]);
                s = __fmaf_rn(acc[mi][ni][3], -2.0f, re1); ins4(s, code + 1, tD[s1], tI[s1]);
            }
        }
        __syncthreads();                 // readers done with buf (c&1)
        if (c + 2 < NCH) {               // prefetch chunk c+2 into freed buffer
            uint32_t dst = smb + SM_B + (c & 1) * B_CH;
            const unsigned char* src = g_eT + (size_t)(c + 2) * B_CH;
            for (int i = tid; i < B_CH / 16; i += TPB)
                cp_async16(dst + i * 16, src + i * 16);
            CP_COMMIT();
        }
    }

    // ---- top-4 merge across lanes (bfly over l&3) ----
#pragma unroll
    for (int s = 0; s < 4; ++s) {
#pragma unroll
        for (int m = 1; m <= 2; m <<= 1) {
            float oD[4]; int oI[4];
#pragma unroll
            for (int r = 0; r < 4; ++r) {
                oD[r] = __shfl_xor_sync(0xffffffffu, tD[s][r], m);
                oI[r] = __shfl_xor_sync(0xffffffffu, tI[s][r], m);
            }
#pragma unroll
            for (int r = 0; r < 4; ++r) ins4(oD[r], oI[r], tD[s], tI[s]);
        }
    }
    if ((l & 3) == 0) {
#pragma unroll
        for (int s = 0; s < 4; ++s) {
            int r = wm * 32 + (l >> 2) + s * 8;
#pragma unroll
            for (int j = 0; j < 4; ++j) {
                sRedD[(r * 2 + wn) * 4 + j] = tD[s][j];
                sRedI[(r * 2 + wn) * 4 + j] = tI[s][j];
            }
        }
    }
    __syncthreads();

    // ---- recheck: 2 threads/row, 4 candidates each, EXACT fp32 ----
    {
        int row = tid >> 1, half = tid & 1;
        const float4* xr = (const float4*)(x + (row0 + row) * DIMV);
        float rx = sRX[row];
        float bD = 3.402823466e38f;
        int   bi = 0x7fffffff;
#pragma unroll
        for (int t = 0; t < 4; ++t) {
            int cd = sRedI[(row * 2 + half) * 4 + t];
            const float4* er = (const float4*)(emb + (size_t)cd * DIMV);
            float a0 = 0.f, a1 = 0.f, a2 = 0.f, a3 = 0.f;
#pragma unroll 8
            for (int j = 0; j < 32; ++j) {
                float4 xv = xr[j], ev = er[j];
                a0 = __fmaf_rn(xv.x, ev.x, a0);
                a1 = __fmaf_rn(xv.y, ev.y, a1);
                a2 = __fmaf_rn(xv.z, ev.z, a2);
                a3 = __fmaf_rn(xv.w, ev.w, a3);
            }
            float m = __fadd_rn(__fadd_rn(a0, a1), __fadd_rn(a2, a3));
            float d = __fadd_rn(__fadd_rn(rx, sRE[cd]), __fmul_rn(m, -2.0f));
            if (lt(d, cd, bD, bi)) { bD = d; bi = cd; }
        }
        float oD = __shfl_xor_sync(0xffffffffu, bD, 1);
        int   oI = __shfl_xor_sync(0xffffffffu, bi, 1);
        if (lt(oD, oI, bD, bi)) { bD = oD; bi = oI; }
        if (!half) {
            sRedI[row * 8] = bi;         // per-row winner
            atomicAdd(&g_counts[bi], 1);
        }
    }
    __syncthreads();

    // ---- fused output: STE-rounded gather + fp64 loss partial ----
    double ls = 0.0;
    {
        const float4* xin4 = (const float4*)(x + row0 * DIMV);
        float4*       o4   = (float4*)(out + row0 * DIMV);
        const float4* e4   = (const float4*)emb;
        for (int i = tid; i < RPB * (DIMV / 4); i += TPB) {
            int rr  = i >> 5;
            int col = i & 31;
            float4 q  = e4[(size_t)sRedI[rr * 8] * 32 + col];
            float4 xv = xin4[i];
            float4 o;
            o.x = __fadd_rn(xv.x, __fadd_rn(q.x, -xv.x));
            o.y = __fadd_rn(xv.y, __fadd_rn(q.y, -xv.y));
            o.z = __fadd_rn(xv.z, __fadd_rn(q.z, -xv.z));
            o.w = __fadd_rn(xv.w, __fadd_rn(q.w, -xv.w));
            o4[i] = o;
            double dx = (double)q.x - xv.x, dy = (double)q.y - xv.y;
            double dz = (double)q.z - xv.z, dw = (double)q.w - xv.w;
            ls += dx * dx + dy * dy + dz * dz + dw * dw;
        }
    }
#pragma unroll
    for (int o = 16; o > 0; o >>= 1) ls += __shfl_down_sync(0xffffffffu, ls, o);
    if (l == 0) sLoss[wid] = ls;
    __syncthreads();
    if (tid == 0) {
        double t = 0.0;
#pragma unroll
        for (int i = 0; i < 8; ++i) t += sLoss[i];
        atomicAdd(&g_loss, t);
        __threadfence();
        unsigned int tk = atomicAdd(&g_ticket, 1u);
        sFlag[0] = (tk == (unsigned int)(NBLOCKS - 1)) ? 1u : 0u;
    }
    __syncthreads();

    // ---- fused finalize (last block only): perplexity + loss scalars ----
    if (sFlag[0]) {
        __threadfence();
        float acc = 0.f;
        for (int k = tid; k < KCODES; k += TPB) {
            float p = (float)__ldcg(&g_counts[k]) * (1.0f / (float)N_ROWS);
            acc += p * logf(p + 1e-10f);
        }
#pragma unroll
        for (int o = 16; o > 0; o >>= 1) acc += __shfl_down_sync(0xffffffffu, acc, o);
        if (l == 0) sRed2[wid] = acc;
        __syncthreads();
        if (tid == 0) {
            float s = 0.f;
#pragma unroll
            for (int i = 0; i < 8; ++i) s += sRed2[i];
            double lv = __ldcg(&g_loss);
            out[out_size - 2] = (float)(1.25 * (lv / (double)(N_ROWS * DIMV)));
            out[out_size - 1] = expf(-s);
        }
    }
}

// ----------------------------------------------------------------
extern "C" void kernel_launch(void* const* d_in, const int* in_sizes, int n_in,
                              void* d_out, int out_size) {
    const float* x   = (const float*)d_in[0];
    const float* emb = (const float*)d_in[1];
    float*       out = (float*)d_out;
    (void)in_sizes; (void)n_in;

    cudaFuncSetAttribute(vq_main, cudaFuncAttributeMaxDynamicSharedMemorySize,
                         SMEM_TOTAL);

    vq_prep<<<8, 256>>>(emb);
    vq_main<<<NBLOCKS, TPB, SMEM_TOTAL>>>(x, emb, out, out_size);
}

// round 14
// speedup vs baseline: 2.0842x; 1.4573x over previous
#include <cuda_runtime.h>
#include <cuda_bf16.h>
#include <cstdint>

// ---------------------------------------------------------------- constants
#define N_ROWS   65536
#define DIMV     128
#define KCODES   1024
#define RPB      128                  // rows per block (M)
#define CPC      64                   // codes per chunk (N)
#define NCH      (KCODES / CPC)       // 16
#define TPB      256
#define NBLOCKS  (N_ROWS / RPB)       // 512

// padded bf16 row: 136 elems = 272 B = 17 x 16B granules (conflict-free ldmatrix)
#define ROWB     272
#define XA_B     (RPB * ROWB)         // 34816
#define B_CH     (CPC * ROWB)         // 17408 per chunk
#define ETB      (KCODES * ROWB)      // 278528

// smem layout (total 78448 -> 2 blocks/SM)
#define SM_XA    0
#define SM_B     XA_B                         // 34816 (double-buffered)
#define SM_RE    (SM_B + 2 * B_CH)            // 69632
#define SM_RX    (SM_RE + KCODES * 4)         // 73728
#define SM_REDI  (SM_RX + RPB * 4)            // 74240 (128 rows x 8 cands)
#define SM_LOSS  (SM_REDI + RPB * 8 * 4)      // 78336
#define SM_RED2  (SM_LOSS + 64)               // 78400
#define SM_FLAG  (SM_RED2 + 32)               // 78432
#define SMEM_TOTAL (SM_FLAG + 16)             // 78448

// ---------------------------------------------------------------- scratch
__device__ float        g_re[KCODES];
__device__ int          g_counts[KCODES];
__device__ double       g_loss;
__device__ unsigned int g_ticket;
// bf16 codebook (rounded), padded rows: [1024][136] bf16
__device__ __align__(16) unsigned char g_eT[ETB];

// ---------------------------------------------------------------- helpers
__device__ __forceinline__ uint32_t smem_u32(const void* p) {
    uint32_t a;
    asm("{ .reg .u64 t; cvta.to.shared.u64 t, %1; cvt.u32.u64 %0, t; }"
        : "=r"(a) : "l"(p));
    return a;
}
static __device__ __forceinline__ void cp_async16(uint32_t dst, const void* src) {
    asm volatile("cp.async.cg.shared.global [%0], [%1], 16;\n" :: "r"(dst), "l"(src));
}
#define CP_COMMIT() asm volatile("cp.async.commit_group;\n" ::: "memory")
#define CP_WAIT1()  asm volatile("cp.async.wait_group 1;\n" ::: "memory")
#define CP_WAIT0()  asm volatile("cp.async.wait_group 0;\n" ::: "memory")

#define LDSM4(r, addr) \
    asm volatile("ldmatrix.sync.aligned.m8n8.x4.shared.b16 {%0,%1,%2,%3}, [%4];" \
        : "=r"((r)[0]), "=r"((r)[1]), "=r"((r)[2]), "=r"((r)[3]) : "r"(addr))

#define MMA16816(c, a, b0, b1) \
    asm volatile("mma.sync.aligned.m16n8k16.row.col.f32.bf16.bf16.f32 " \
        "{%0,%1,%2,%3}, {%4,%5,%6,%7}, {%8,%9}, {%0,%1,%2,%3};" \
        : "+f"((c)[0]), "+f"((c)[1]), "+f"((c)[2]), "+f"((c)[3]) \
        : "r"((a)[0]), "r"((a)[1]), "r"((a)[2]), "r"((a)[3]), "r"(b0), "r"(b1))

// ordering with index tie-break (exact recheck only)
static __device__ __forceinline__ bool lt(float dA, int iA, float dB, int iB) {
    return dA < dB || (dA == dB && iA < iB);
}
// BRANCHLESS top-2 insert (capture semantics: strict < keeps earlier index)
static __device__ __forceinline__ void ins2b(float d, int i,
                                             float& bD, int& bI, float& sD, int& sI) {
    bool p = d < bD;
    float lD = p ? bD : d;  int lI = p ? bI : i;   // loser of first compare
    bD = p ? d : bD;        bI = p ? i : bI;
    bool q = lD < sD;
    sD = q ? lD : sD;       sI = q ? lI : sI;
}

// ---------------------------------------------------------------- prep
// 2 threads per code: ||e||^2 (fp32 squares, fp64 sum -> fp32) + bf16 tile.
__global__ void vq_prep(const float* __restrict__ emb) {
    int g = blockIdx.x * blockDim.x + threadIdx.x;   // 0..2047
    int k = g >> 1, half = g & 1;
    const float4* e4 = (const float4*)(emb + (size_t)k * DIMV + half * 64);
    unsigned char* base = g_eT + (size_t)k * ROWB + half * 128;
    double s = 0.0;
#pragma unroll
    for (int i = 0; i < 16; ++i) {
        float4 v = e4[i];
        s += (double)__fmul_rn(v.x, v.x) + (double)__fmul_rn(v.y, v.y)
           + (double)__fmul_rn(v.z, v.z) + (double)__fmul_rn(v.w, v.w);
        *(__nv_bfloat162*)(base + i * 8)     =
            __halves2bfloat162(__float2bfloat16_rn(v.x), __float2bfloat16_rn(v.y));
        *(__nv_bfloat162*)(base + i * 8 + 4) =
            __halves2bfloat162(__float2bfloat16_rn(v.z), __float2bfloat16_rn(v.w));
    }
    s += __shfl_xor_sync(0xffffffffu, s, 1);
    if (!half) { g_re[k] = (float)s; g_counts[k] = 0; }
    if (g == 0) { g_loss = 0.0; g_ticket = 0u; }
}

// ---------------------------------------------------------------- main
__global__ __launch_bounds__(TPB, 2)
void vq_main(const float* __restrict__ x, const float* __restrict__ emb,
             float* __restrict__ out, int out_size) {
    extern __shared__ __align__(16) char sm[];
    float*  sRE   = (float*)(sm + SM_RE);
    float*  sRX   = (float*)(sm + SM_RX);
    int*    sRedI = (int*)  (sm + SM_REDI);
    double* sLoss = (double*)(sm + SM_LOSS);
    float*  sRed2 = (float*)(sm + SM_RED2);
    unsigned int* sFlag = (unsigned int*)(sm + SM_FLAG);

    const uint32_t smb = smem_u32(sm);
    const int tid = threadIdx.x, wid = tid >> 5, l = tid & 31;
    const int wm = wid & 3, wn = wid >> 2;          // 4 x 2 warp grid
    const size_t row0 = (size_t)blockIdx.x * RPB;

    // ---- prefetch B chunks 0,1 (double-buffered) ----
#pragma unroll
    for (int c = 0; c < 2; ++c) {
        uint32_t dst = smb + SM_B + c * B_CH;
        const unsigned char* src = g_eT + (size_t)c * B_CH;
        for (int i = tid; i < B_CH / 16; i += TPB)
            cp_async16(dst + i * 16, src + i * 16);
        CP_COMMIT();
    }

    // ---- stage x (bf16, padded) + fp64 row norms ----
    {
        int row = tid >> 1, half = tid & 1;
        const float4* xr = (const float4*)(x + (row0 + row) * DIMV + half * 64);
        char* base = sm + SM_XA + row * ROWB + half * 128;
        double s = 0.0;
#pragma unroll
        for (int i = 0; i < 16; ++i) {
            float4 v = xr[i];
            s += (double)__fmul_rn(v.x, v.x) + (double)__fmul_rn(v.y, v.y)
               + (double)__fmul_rn(v.z, v.z) + (double)__fmul_rn(v.w, v.w);
            *(__nv_bfloat162*)(base + i * 8)     =
                __halves2bfloat162(__float2bfloat16_rn(v.x), __float2bfloat16_rn(v.y));
            *(__nv_bfloat162*)(base + i * 8 + 4) =
                __halves2bfloat162(__float2bfloat16_rn(v.z), __float2bfloat16_rn(v.w));
        }
        s += __shfl_xor_sync(0xffffffffu, s, 1);
        if (!half) sRX[row] = (float)s;
    }
    for (int i = tid; i < KCODES; i += TPB) sRE[i] = g_re[i];
    __syncthreads();   // staging of A/rx visible

    uint32_t aAddr[2];
#pragma unroll
    for (int mi = 0; mi < 2; ++mi)
        aAddr[mi] = smb + SM_XA
                  + (wm * 32 + mi * 16 + (l & 15)) * ROWB + ((l >> 4) & 1) * 16;
    uint32_t bOff[2];
#pragma unroll
    for (int g = 0; g < 2; ++g)
        bOff[g] = (wn * 32 + g * 16 + (l & 7) + ((l >> 4) & 1) * 8) * ROWB
                + ((l >> 3) & 1) * 16;

    // per-slot top-2 (4 row-slots per thread), branchless maintenance
    float bD[4], sD[4];
    int   bI[4], sI[4];
#pragma unroll
    for (int s = 0; s < 4; ++s) { bD[s] = sD[s] = 3.402823466e38f; bI[s] = sI[s] = 0; }

#pragma unroll 1
    for (int c = 0; c < NCH; ++c) {
        if (c + 1 < NCH) CP_WAIT1(); else CP_WAIT0();
        __syncthreads();                 // buf (c&1) ready for all
        uint32_t bB = smb + SM_B + (c & 1) * B_CH;

        float acc[2][4][4];
#pragma unroll
        for (int mi = 0; mi < 2; ++mi)
#pragma unroll
            for (int ni = 0; ni < 4; ++ni)
#pragma unroll
                for (int q = 0; q < 4; ++q) acc[mi][ni][q] = 0.f;

#pragma unroll
        for (int ks = 0; ks < 8; ++ks) {
            uint32_t A[2][4], B[2][4];
            LDSM4(A[0], aAddr[0] + ks * 32);
            LDSM4(A[1], aAddr[1] + ks * 32);
            LDSM4(B[0], bB + bOff[0] + ks * 32);
            LDSM4(B[1], bB + bOff[1] + ks * 32);
#pragma unroll
            for (int mi = 0; mi < 2; ++mi)
#pragma unroll
                for (int ni = 0; ni < 4; ++ni)
                    MMA16816(acc[mi][ni], A[mi],
                             B[ni >> 1][(ni & 1) * 2], B[ni >> 1][(ni & 1) * 2 + 1]);
        }

        // epilogue: selection metric s = re - 2*m (rx restored in recheck)
        int cb = c * CPC + wn * 32;
#pragma unroll
        for (int mi = 0; mi < 2; ++mi) {
#pragma unroll
            for (int ni = 0; ni < 4; ++ni) {
                int code = cb + ni * 8 + 2 * (l & 3);
                float re0 = sRE[code], re1 = sRE[code + 1];
                int s0 = mi * 2, s1 = mi * 2 + 1;
                float s;
                s = __fmaf_rn(acc[mi][ni][0], -2.0f, re0);
                ins2b(s, code,     bD[s0], bI[s0], sD[s0], sI[s0]);
                s = __fmaf_rn(acc[mi][ni][1], -2.0f, re1);
                ins2b(s, code + 1, bD[s0], bI[s0], sD[s0], sI[s0]);
                s = __fmaf_rn(acc[mi][ni][2], -2.0f, re0);
                ins2b(s, code,     bD[s1], bI[s1], sD[s1], sI[s1]);
                s = __fmaf_rn(acc[mi][ni][3], -2.0f, re1);
                ins2b(s, code + 1, bD[s1], bI[s1], sD[s1], sI[s1]);
            }
        }
        __syncthreads();                 // readers done with buf (c&1)
        if (c + 2 < NCH) {               // prefetch chunk c+2 into freed buffer
            uint32_t dst = smb + SM_B + (c & 1) * B_CH;
            const unsigned char* src = g_eT + (size_t)(c + 2) * B_CH;
            for (int i = tid; i < B_CH / 16; i += TPB)
                cp_async16(dst + i * 16, src + i * 16);
            CP_COMMIT();
        }
    }

    // ---- one xor-2 merge (branchless), then dump 8 candidates per row ----
#pragma unroll
    for (int s = 0; s < 4; ++s) {
        float obD = __shfl_xor_sync(0xffffffffu, bD[s], 2);
        int   obI = __shfl_xor_sync(0xffffffffu, bI[s], 2);
        float osD = __shfl_xor_sync(0xffffffffu, sD[s], 2);
        int   osI = __shfl_xor_sync(0xffffffffu, sI[s], 2);
        ins2b(obD, obI, bD[s], bI[s], sD[s], sI[s]);
        ins2b(osD, osI, bD[s], bI[s], sD[s], sI[s]);
    }
    if ((l & 3) < 2) {
#pragma unroll
        for (int s = 0; s < 4; ++s) {
            int r = wm * 32 + (l >> 2) + s * 8;
            int base = r * 8 + wn * 4 + (l & 3) * 2;
            sRedI[base]     = bI[s];
            sRedI[base + 1] = sI[s];
        }
    }
    __syncthreads();

    // ---- recheck: 2 threads/row, 4 candidates each, EXACT fp32 ----
    {
        int row = tid >> 1, half = tid & 1;
        const float4* xr = (const float4*)(x + (row0 + row) * DIMV);
        float rx = sRX[row];
        float fD = 3.402823466e38f;
        int   fI = 0x7fffffff;
#pragma unroll
        for (int t = 0; t < 4; ++t) {
            int cd = sRedI[row * 8 + half * 4 + t];
            const float4* er = (const float4*)(emb + (size_t)cd * DIMV);
            float a0 = 0.f, a1 = 0.f, a2 = 0.f, a3 = 0.f;
#pragma unroll 8
            for (int j = 0; j < 32; ++j) {
                float4 xv = xr[j], ev = er[j];
                a0 = __fmaf_rn(xv.x, ev.x, a0);
                a1 = __fmaf_rn(xv.y, ev.y, a1);
                a2 = __fmaf_rn(xv.z, ev.z, a2);
                a3 = __fmaf_rn(xv.w, ev.w, a3);
            }
            float m = __fadd_rn(__fadd_rn(a0, a1), __fadd_rn(a2, a3));
            float d = __fadd_rn(__fadd_rn(rx, sRE[cd]), __fmul_rn(m, -2.0f));
            if (lt(d, cd, fD, fI)) { fD = d; fI = cd; }
        }
        float oD = __shfl_xor_sync(0xffffffffu, fD, 1);
        int   oI = __shfl_xor_sync(0xffffffffu, fI, 1);
        if (lt(oD, oI, fD, fI)) { fD = oD; fI = oI; }
        if (!half) {
            sRedI[row * 8] = fI;         // per-row winner
            atomicAdd(&g_counts[fI], 1);
        }
    }
    __syncthreads();

    // ---- fused output: STE-rounded gather + fp64 loss partial ----
    double ls = 0.0;
    {
        const float4* xin4 = (const float4*)(x + row0 * DIMV);
        float4*       o4   = (float4*)(out + row0 * DIMV);
        const float4* e4   = (const float4*)emb;
        for (int i = tid; i < RPB * (DIMV / 4); i += TPB) {
            int rr  = i >> 5;
            int col = i & 31;
            float4 q  = e4[(size_t)sRedI[rr * 8] * 32 + col];
            float4 xv = xin4[i];
            float4 o;
            o.x = __fadd_rn(xv.x, __fadd_rn(q.x, -xv.x));
            o.y = __fadd_rn(xv.y, __fadd_rn(q.y, -xv.y));
            o.z = __fadd_rn(xv.z, __fadd_rn(q.z, -xv.z));
            o.w = __fadd_rn(xv.w, __fadd_rn(q.w, -xv.w));
            o4[i] = o;
            double dx = (double)q.x - xv.x, dy = (double)q.y - xv.y;
            double dz = (double)q.z - xv.z, dw = (double)q.w - xv.w;
            ls += dx * dx + dy * dy + dz * dz + dw * dw;
        }
    }
#pragma unroll
    for (int o = 16; o > 0; o >>= 1) ls += __shfl_down_sync(0xffffffffu, ls, o);
    if (l == 0) sLoss[wid] = ls;
    __syncthreads();
    if (tid == 0) {
        double t = 0.0;
#pragma unroll
        for (int i = 0; i < 8; ++i) t += sLoss[i];
        atomicAdd(&g_loss, t);
        __threadfence();
        unsigned int tk = atomicAdd(&g_ticket, 1u);
        sFlag[0] = (tk == (unsigned int)(NBLOCKS - 1)) ? 1u : 0u;
    }
    __syncthreads();

    // ---- fused finalize (last block only): perplexity + loss scalars ----
    if (sFlag[0]) {
        __threadfence();
        float acc = 0.f;
        for (int k = tid; k < KCODES; k += TPB) {
            float p = (float)__ldcg(&g_counts[k]) * (1.0f / (float)N_ROWS);
            acc += p * logf(p + 1e-10f);
        }
#pragma unroll
        for (int o = 16; o > 0; o >>= 1) acc += __shfl_down_sync(0xffffffffu, acc, o);
        if (l == 0) sRed2[wid] = acc;
        __syncthreads();
        if (tid == 0) {
            float s = 0.f;
#pragma unroll
            for (int i = 0; i < 8; ++i) s += sRed2[i];
            double lv = __ldcg(&g_loss);
            out[out_size - 2] = (float)(1.25 * (lv / (double)(N_ROWS * DIMV)));
            out[out_size - 1] = expf(-s);
        }
    }
}

// ----------------------------------------------------------------
extern "C" void kernel_launch(void* const* d_in, const int* in_sizes, int n_in,
                              void* d_out, int out_size) {
    const float* x   = (const float*)d_in[0];
    const float* emb = (const float*)d_in[1];
    float*       out = (float*)d_out;
    (void)in_sizes; (void)n_in;

    cudaFuncSetAttribute(vq_main, cudaFuncAttributeMaxDynamicSharedMemorySize,
                         SMEM_TOTAL);

    vq_prep<<<8, 256>>>(emb);
    vq_main<<<NBLOCKS, TPB, SMEM_TOTAL>>>(x, emb, out, out_size);
}

// round 15
// speedup vs baseline: 2.6428x; 1.2680x over previous
#include <cuda_runtime.h>
#include <cuda_bf16.h>
#include <cstdint>

// ---------------------------------------------------------------- constants
#define N_ROWS   65536
#define DIMV     128
#define KCODES   1024
#define RPB      128                  // rows per block (M)
#define CPC      64                   // codes per chunk (N)
#define NCH      (KCODES / CPC)       // 16
#define TPB      256
#define NBLOCKS  (N_ROWS / RPB)       // 512

// padded bf16 row: 136 elems = 272 B = 17 x 16B granules (conflict-free ldmatrix)
#define ROWB     272
#define XA_B     (RPB * ROWB)         // 34816
#define B_CH     (CPC * ROWB)         // 17408 per chunk
#define ETB      (KCODES * ROWB)      // 278528

// smem layout (total 78448 -> 2 blocks/SM)
#define SM_XA    0
#define SM_B     XA_B                         // 34816 (double-buffered)
#define SM_RE    (SM_B + 2 * B_CH)            // 69632
#define SM_RX    (SM_RE + KCODES * 4)         // 73728
#define SM_REDI  (SM_RX + RPB * 4)            // 74240 (128 rows x 8 cands)
#define SM_LOSS  (SM_REDI + RPB * 8 * 4)      // 78336
#define SM_RED2  (SM_LOSS + 64)               // 78400
#define SM_FLAG  (SM_RED2 + 32)               // 78432
#define SMEM_TOTAL (SM_FLAG + 16)             // 78448

// ---------------------------------------------------------------- scratch
__device__ float        g_re[KCODES];
__device__ int          g_counts[KCODES];
__device__ double       g_loss;
__device__ unsigned int g_ticket;
// bf16 codebook (rounded), padded rows: [1024][136] bf16
__device__ __align__(16) unsigned char g_eT[ETB];

// ---------------------------------------------------------------- helpers
__device__ __forceinline__ uint32_t smem_u32(const void* p) {
    uint32_t a;
    asm("{ .reg .u64 t; cvta.to.shared.u64 t, %1; cvt.u32.u64 %0, t; }"
        : "=r"(a) : "l"(p));
    return a;
}
static __device__ __forceinline__ void cp_async16(uint32_t dst, const void* src) {
    asm volatile("cp.async.cg.shared.global [%0], [%1], 16;\n" :: "r"(dst), "l"(src));
}
#define CP_COMMIT() asm volatile("cp.async.commit_group;\n" ::: "memory")
#define CP_WAIT1()  asm volatile("cp.async.wait_group 1;\n" ::: "memory")
#define CP_WAIT0()  asm volatile("cp.async.wait_group 0;\n" ::: "memory")

#define LDSM4(r, addr) \
    asm volatile("ldmatrix.sync.aligned.m8n8.x4.shared.b16 {%0,%1,%2,%3}, [%4];" \
        : "=r"((r)[0]), "=r"((r)[1]), "=r"((r)[2]), "=r"((r)[3]) : "r"(addr))

#define MMA16816(c, a, b0, b1) \
    asm volatile("mma.sync.aligned.m16n8k16.row.col.f32.bf16.bf16.f32 " \
        "{%0,%1,%2,%3}, {%4,%5,%6,%7}, {%8,%9}, {%0,%1,%2,%3};" \
        : "+f"((c)[0]), "+f"((c)[1]), "+f"((c)[2]), "+f"((c)[3]) \
        : "r"((a)[0]), "r"((a)[1]), "r"((a)[2]), "r"((a)[3]), "r"(b0), "r"(b1))

// ordering with index tie-break (exact recheck only)
static __device__ __forceinline__ bool lt(float dA, int iA, float dB, int iB) {
    return dA < dB || (dA == dB && iA < iB);
}
// BRANCHLESS top-2 insert (capture semantics: strict < keeps earlier index)
static __device__ __forceinline__ void ins2b(float d, int i,
                                             float& bD, int& bI, float& sD, int& sI) {
    bool p = d < bD;
    float lD = p ? bD : d;  int lI = p ? bI : i;   // loser of first compare
    bD = p ? d : bD;        bI = p ? i : bI;
    bool q = lD < sD;
    sD = q ? lD : sD;       sI = q ? lI : sI;
}

// ---------------------------------------------------------------- prep
// 4 threads per code: ||e||^2 (fp32 squares, fp64 sum -> fp32) + bf16 tile.
__global__ void vq_prep(const float* __restrict__ emb) {
    int g = blockIdx.x * blockDim.x + threadIdx.x;   // 0..4095
    int k = g >> 2, q = g & 3;
    const float4* e4 = (const float4*)(emb + (size_t)k * DIMV + q * 32);
    unsigned char* base = g_eT + (size_t)k * ROWB + q * 64;
    double s = 0.0;
#pragma unroll
    for (int i = 0; i < 8; ++i) {
        float4 v = e4[i];
        s += (double)__fmul_rn(v.x, v.x) + (double)__fmul_rn(v.y, v.y)
           + (double)__fmul_rn(v.z, v.z) + (double)__fmul_rn(v.w, v.w);
        *(__nv_bfloat162*)(base + i * 8)     =
            __halves2bfloat162(__float2bfloat16_rn(v.x), __float2bfloat16_rn(v.y));
        *(__nv_bfloat162*)(base + i * 8 + 4) =
            __halves2bfloat162(__float2bfloat16_rn(v.z), __float2bfloat16_rn(v.w));
    }
    s += __shfl_xor_sync(0xffffffffu, s, 1);
    s += __shfl_xor_sync(0xffffffffu, s, 2);
    if (q == 0) { g_re[k] = (float)s; g_counts[k] = 0; }
    if (g == 0) { g_loss = 0.0; g_ticket = 0u; }
}

// ---------------------------------------------------------------- main
__global__ __launch_bounds__(TPB, 2)
void vq_main(const float* __restrict__ x, const float* __restrict__ emb,
             float* __restrict__ out, int out_size) {
    extern __shared__ __align__(16) char sm[];
    float*  sRE   = (float*)(sm + SM_RE);
    float*  sRX   = (float*)(sm + SM_RX);
    int*    sRedI = (int*)  (sm + SM_REDI);
    double* sLoss = (double*)(sm + SM_LOSS);
    float*  sRed2 = (float*)(sm + SM_RED2);
    unsigned int* sFlag = (unsigned int*)(sm + SM_FLAG);

    const uint32_t smb = smem_u32(sm);
    const int tid = threadIdx.x, wid = tid >> 5, l = tid & 31;
    const int wm = wid & 3, wn = wid >> 2;          // 4 x 2 warp grid
    const size_t row0 = (size_t)blockIdx.x * RPB;

    // ---- prefetch B chunks 0,1 (double-buffered) ----
#pragma unroll
    for (int c = 0; c < 2; ++c) {
        uint32_t dst = smb + SM_B + c * B_CH;
        const unsigned char* src = g_eT + (size_t)c * B_CH;
        for (int i = tid; i < B_CH / 16; i += TPB)
            cp_async16(dst + i * 16, src + i * 16);
        CP_COMMIT();
    }

    // ---- stage x (bf16, padded) + fp64 row norms ----
    {
        int row = tid >> 1, half = tid & 1;
        const float4* xr = (const float4*)(x + (row0 + row) * DIMV + half * 64);
        char* base = sm + SM_XA + row * ROWB + half * 128;
        double s = 0.0;
#pragma unroll
        for (int i = 0; i < 16; ++i) {
            float4 v = xr[i];
            s += (double)__fmul_rn(v.x, v.x) + (double)__fmul_rn(v.y, v.y)
               + (double)__fmul_rn(v.z, v.z) + (double)__fmul_rn(v.w, v.w);
            *(__nv_bfloat162*)(base + i * 8)     =
                __halves2bfloat162(__float2bfloat16_rn(v.x), __float2bfloat16_rn(v.y));
            *(__nv_bfloat162*)(base + i * 8 + 4) =
                __halves2bfloat162(__float2bfloat16_rn(v.z), __float2bfloat16_rn(v.w));
        }
        s += __shfl_xor_sync(0xffffffffu, s, 1);
        if (!half) sRX[row] = (float)s;
    }
    for (int i = tid; i < KCODES; i += TPB) sRE[i] = g_re[i];
    __syncthreads();   // staging of A/rx visible

    uint32_t aAddr[2];
#pragma unroll
    for (int mi = 0; mi < 2; ++mi)
        aAddr[mi] = smb + SM_XA
                  + (wm * 32 + mi * 16 + (l & 15)) * ROWB + ((l >> 4) & 1) * 16;
    uint32_t bOff[2];
#pragma unroll
    for (int g = 0; g < 2; ++g)
        bOff[g] = (wn * 32 + g * 16 + (l & 7) + ((l >> 4) & 1) * 8) * ROWB
                + ((l >> 3) & 1) * 16;

    // per-slot top-2 (4 row-slots per thread), branchless maintenance
    float bD[4], sD[4];
    int   bI[4], sI[4];
#pragma unroll
    for (int s = 0; s < 4; ++s) { bD[s] = sD[s] = 3.402823466e38f; bI[s] = sI[s] = 0; }

#pragma unroll 1
    for (int c = 0; c < NCH; ++c) {
        if (c + 1 < NCH) CP_WAIT1(); else CP_WAIT0();
        __syncthreads();                 // buf (c&1) ready for all
        uint32_t bB = smb + SM_B + (c & 1) * B_CH;

        float acc[2][4][4];
#pragma unroll
        for (int mi = 0; mi < 2; ++mi)
#pragma unroll
            for (int ni = 0; ni < 4; ++ni)
#pragma unroll
                for (int q = 0; q < 4; ++q) acc[mi][ni][q] = 0.f;

#pragma unroll
        for (int ks = 0; ks < 8; ++ks) {
            uint32_t A[2][4], B[2][4];
            LDSM4(A[0], aAddr[0] + ks * 32);
            LDSM4(A[1], aAddr[1] + ks * 32);
            LDSM4(B[0], bB + bOff[0] + ks * 32);
            LDSM4(B[1], bB + bOff[1] + ks * 32);
#pragma unroll
            for (int mi = 0; mi < 2; ++mi)
#pragma unroll
                for (int ni = 0; ni < 4; ++ni)
                    MMA16816(acc[mi][ni], A[mi],
                             B[ni >> 1][(ni & 1) * 2], B[ni >> 1][(ni & 1) * 2 + 1]);
        }

        // epilogue: selection metric s = re - 2*m (rx restored in recheck)
        int cb = c * CPC + wn * 32;
#pragma unroll
        for (int mi = 0; mi < 2; ++mi) {
#pragma unroll
            for (int ni = 0; ni < 4; ++ni) {
                int code = cb + ni * 8 + 2 * (l & 3);
                float re0 = sRE[code], re1 = sRE[code + 1];
                int s0 = mi * 2, s1 = mi * 2 + 1;
                float s;
                s = __fmaf_rn(acc[mi][ni][0], -2.0f, re0);
                ins2b(s, code,     bD[s0], bI[s0], sD[s0], sI[s0]);
                s = __fmaf_rn(acc[mi][ni][1], -2.0f, re1);
                ins2b(s, code + 1, bD[s0], bI[s0], sD[s0], sI[s0]);
                s = __fmaf_rn(acc[mi][ni][2], -2.0f, re0);
                ins2b(s, code,     bD[s1], bI[s1], sD[s1], sI[s1]);
                s = __fmaf_rn(acc[mi][ni][3], -2.0f, re1);
                ins2b(s, code + 1, bD[s1], bI[s1], sD[s1], sI[s1]);
            }
        }
        __syncthreads();                 // readers done with buf (c&1)
        if (c + 2 < NCH) {               // prefetch chunk c+2 into freed buffer
            uint32_t dst = smb + SM_B + (c & 1) * B_CH;
            const unsigned char* src = g_eT + (size_t)(c + 2) * B_CH;
            for (int i = tid; i < B_CH / 16; i += TPB)
                cp_async16(dst + i * 16, src + i * 16);
            CP_COMMIT();
        }
    }

    // ---- one xor-2 merge (branchless), then dump 8 candidates per row ----
#pragma unroll
    for (int s = 0; s < 4; ++s) {
        float obD = __shfl_xor_sync(0xffffffffu, bD[s], 2);
        int   obI = __shfl_xor_sync(0xffffffffu, bI[s], 2);
        float osD = __shfl_xor_sync(0xffffffffu, sD[s], 2);
        int   osI = __shfl_xor_sync(0xffffffffu, sI[s], 2);
        ins2b(obD, obI, bD[s], bI[s], sD[s], sI[s]);
        ins2b(osD, osI, bD[s], bI[s], sD[s], sI[s]);
    }
    if ((l & 3) < 2) {
#pragma unroll
        for (int s = 0; s < 4; ++s) {
            int r = wm * 32 + (l >> 2) + s * 8;
            int base = r * 8 + wn * 4 + (l & 3) * 2;
            sRedI[base]     = bI[s];
            sRedI[base + 1] = sI[s];
        }
    }
    __syncthreads();

    // ---- recheck: 1 warp per row, fully coalesced, EXACT fp32 ----
    {
        const float4* e4 = (const float4*)emb;
#pragma unroll 1
        for (int it = 0; it < 16; ++it) {
            int row = wid * 16 + it;
            float4 xv = ((const float4*)(x + (row0 + row) * DIMV))[l];
            float rx = sRX[row];
            float fD = 3.402823466e38f;
            int   fI = 0x7fffffff;
#pragma unroll
            for (int t = 0; t < 8; ++t) {
                int cd = sRedI[row * 8 + t];
                float4 ev = e4[(size_t)cd * 32 + l];
                float p = __fmaf_rn(xv.x, ev.x,
                          __fmaf_rn(xv.y, ev.y,
                          __fmaf_rn(xv.z, ev.z, __fmul_rn(xv.w, ev.w))));
#pragma unroll
                for (int o = 16; o > 0; o >>= 1)
                    p = __fadd_rn(p, __shfl_xor_sync(0xffffffffu, p, o));
                float d = __fadd_rn(__fadd_rn(rx, sRE[cd]), __fmul_rn(p, -2.0f));
                if (lt(d, cd, fD, fI)) { fD = d; fI = cd; }
            }
            if (l == 0) {
                sRedI[row * 8] = fI;     // per-row winner
                atomicAdd(&g_counts[fI], 1);
            }
        }
    }
    __syncthreads();

    // ---- fused output: STE-rounded gather + fp64 loss partial ----
    double ls = 0.0;
    {
        const float4* xin4 = (const float4*)(x + row0 * DIMV);
        float4*       o4   = (float4*)(out + row0 * DIMV);
        const float4* e4   = (const float4*)emb;
        for (int i = tid; i < RPB * (DIMV / 4); i += TPB) {
            int rr  = i >> 5;
            int col = i & 31;
            float4 q  = e4[(size_t)sRedI[rr * 8] * 32 + col];
            float4 xv = xin4[i];
            float4 o;
            o.x = __fadd_rn(xv.x, __fadd_rn(q.x, -xv.x));
            o.y = __fadd_rn(xv.y, __fadd_rn(q.y, -xv.y));
            o.z = __fadd_rn(xv.z, __fadd_rn(q.z, -xv.z));
            o.w = __fadd_rn(xv.w, __fadd_rn(q.w, -xv.w));
            o4[i] = o;
            double dx = (double)q.x - xv.x, dy = (double)q.y - xv.y;
            double dz = (double)q.z - xv.z, dw = (double)q.w - xv.w;
            ls += dx * dx + dy * dy + dz * dz + dw * dw;
        }
    }
#pragma unroll
    for (int o = 16; o > 0; o >>= 1) ls += __shfl_down_sync(0xffffffffu, ls, o);
    if (l == 0) sLoss[wid] = ls;
    __syncthreads();
    if (tid == 0) {
        double t = 0.0;
#pragma unroll
        for (int i = 0; i < 8; ++i) t += sLoss[i];
        atomicAdd(&g_loss, t);
        __threadfence();
        unsigned int tk = atomicAdd(&g_ticket, 1u);
        sFlag[0] = (tk == (unsigned int)(NBLOCKS - 1)) ? 1u : 0u;
    }
    __syncthreads();

    // ---- fused finalize (last block only): perplexity + loss scalars ----
    if (sFlag[0]) {
        __threadfence();
        float acc = 0.f;
        for (int k = tid; k < KCODES; k += TPB) {
            float p = (float)__ldcg(&g_counts[k]) * (1.0f / (float)N_ROWS);
            acc += p * logf(p + 1e-10f);
        }
#pragma unroll
        for (int o = 16; o > 0; o >>= 1) acc += __shfl_down_sync(0xffffffffu, acc, o);
        if (l == 0) sRed2[wid] = acc;
        __syncthreads();
        if (tid == 0) {
            float s = 0.f;
#pragma unroll
            for (int i = 0; i < 8; ++i) s += sRed2[i];
            double lv = __ldcg(&g_loss);
            out[out_size - 2] = (float)(1.25 * (lv / (double)(N_ROWS * DIMV)));
            out[out_size - 1] = expf(-s);
        }
    }
}

// ----------------------------------------------------------------
extern "C" void kernel_launch(void* const* d_in, const int* in_sizes, int n_in,
                              void* d_out, int out_size) {
    const float* x   = (const float*)d_in[0];
    const float* emb = (const float*)d_in[1];
    float*       out = (float*)d_out;
    (void)in_sizes; (void)n_in;

    cudaFuncSetAttribute(vq_main, cudaFuncAttributeMaxDynamicSharedMemorySize,
                         SMEM_TOTAL);

    vq_prep<<<16, 256>>>(emb);
    vq_main<<<NBLOCKS, TPB, SMEM_TOTAL>>>(x, emb, out, out_size);
}

// round 16
// speedup vs baseline: 4.1161x; 1.5575x over previous
#include <cuda_runtime.h>
#include <cuda_bf16.h>
#include <cstdint>

// ---------------------------------------------------------------- constants
#define N_ROWS   65536
#define DIMV     128
#define KCODES   1024
#define RPB      128                  // rows per block (M)
#define CPC      64                   // codes per chunk (N)
#define NCH      (KCODES / CPC)       // 16
#define TPB      256
#define NBLOCKS  (N_ROWS / RPB)       // 512

// padded bf16 row: 136 elems = 272 B = 17 x 16B granules (conflict-free ldmatrix)
#define ROWB     272
#define XA_B     (RPB * ROWB)         // 34816
#define B_CH     (CPC * ROWB)         // 17408 per chunk
#define ETB      (KCODES * ROWB)      // 278528

// smem layout (total 74352 -> 3 blocks/SM)
#define SM_XA    0
#define SM_B     XA_B                         // 34816 (double-buffered)
#define SM_RE    (SM_B + 2 * B_CH)            // 69632 (stores ||e||^2 * 2^20)
#define SM_RX    (SM_RE + KCODES * 4)         // 73728
#define SM_LOSS  (SM_RX + RPB * 4)            // 74240
#define SM_RED2  (SM_LOSS + 64)               // 74304
#define SM_FLAG  (SM_RED2 + 32)               // 74336
#define SM_REDI  SM_B                         // ALIAS: candidates written after
                                              // all B reads complete (sync-ordered)
#define SMEM_TOTAL (SM_FLAG + 16)             // 74352

#define KSCALE   1048576.0f            // 2^20
#define KUNSCALE 9.5367431640625e-7f   // 2^-20 (exact)
#define KM2      -2097152.0f           // -2 * 2^20

// ---------------------------------------------------------------- scratch
__device__ float        g_re[KCODES];   // ||e||^2 * 2^20
__device__ int          g_counts[KCODES];
__device__ double       g_loss;
__device__ unsigned int g_ticket;
// bf16 codebook (rounded), padded rows: [1024][136] bf16
__device__ __align__(16) unsigned char g_eT[ETB];

// ---------------------------------------------------------------- helpers
__device__ __forceinline__ uint32_t smem_u32(const void* p) {
    uint32_t a;
    asm("{ .reg .u64 t; cvta.to.shared.u64 t, %1; cvt.u32.u64 %0, t; }"
        : "=r"(a) : "l"(p));
    return a;
}
static __device__ __forceinline__ void cp_async16(uint32_t dst, const void* src) {
    asm volatile("cp.async.cg.shared.global [%0], [%1], 16;\n" :: "r"(dst), "l"(src));
}
#define CP_COMMIT() asm volatile("cp.async.commit_group;\n" ::: "memory")
#define CP_WAIT1()  asm volatile("cp.async.wait_group 1;\n" ::: "memory")
#define CP_WAIT0()  asm volatile("cp.async.wait_group 0;\n" ::: "memory")

#define LDSM4(r, addr) \
    asm volatile("ldmatrix.sync.aligned.m8n8.x4.shared.b16 {%0,%1,%2,%3}, [%4];" \
        : "=r"((r)[0]), "=r"((r)[1]), "=r"((r)[2]), "=r"((r)[3]) : "r"(addr))

#define MMA16816(c, a, b0, b1) \
    asm volatile("mma.sync.aligned.m16n8k16.row.col.f32.bf16.bf16.f32 " \
        "{%0,%1,%2,%3}, {%4,%5,%6,%7}, {%8,%9}, {%0,%1,%2,%3};" \
        : "+f"((c)[0]), "+f"((c)[1]), "+f"((c)[2]), "+f"((c)[3]) \
        : "r"((a)[0]), "r"((a)[1]), "r"((a)[2]), "r"((a)[3]), "r"(b0), "r"(b1))

// ordering with index tie-break (exact recheck only)
static __device__ __forceinline__ bool lt(float dA, int iA, float dB, int iB) {
    return dA < dB || (dA == dB && iA < iB);
}
// integer top-2 insert: 3 IMNMX, no predicates
#define INSK(key, kb, ks) do {                         \
    int _mn = min((key), (kb)), _mx = max((key), (kb)); \
    (kb) = _mn; (ks) = min((ks), _mx);                  \
} while (0)

// ---------------------------------------------------------------- prep
// 4 threads per code: ||e||^2 (fp32 squares, fp64 sum -> fp32, *2^20) + bf16 tile.
__global__ void vq_prep(const float* __restrict__ emb) {
    int g = blockIdx.x * blockDim.x + threadIdx.x;   // 0..4095
    int k = g >> 2, q = g & 3;
    const float4* e4 = (const float4*)(emb + (size_t)k * DIMV + q * 32);
    unsigned char* base = g_eT + (size_t)k * ROWB + q * 64;
    double s = 0.0;
#pragma unroll
    for (int i = 0; i < 8; ++i) {
        float4 v = e4[i];
        s += (double)__fmul_rn(v.x, v.x) + (double)__fmul_rn(v.y, v.y)
           + (double)__fmul_rn(v.z, v.z) + (double)__fmul_rn(v.w, v.w);
        *(__nv_bfloat162*)(base + i * 8)     =
            __halves2bfloat162(__float2bfloat16_rn(v.x), __float2bfloat16_rn(v.y));
        *(__nv_bfloat162*)(base + i * 8 + 4) =
            __halves2bfloat162(__float2bfloat16_rn(v.z), __float2bfloat16_rn(v.w));
    }
    s += __shfl_xor_sync(0xffffffffu, s, 1);
    s += __shfl_xor_sync(0xffffffffu, s, 2);
    if (q == 0) { g_re[k] = (float)s * KSCALE; g_counts[k] = 0; }
    if (g == 0) { g_loss = 0.0; g_ticket = 0u; }
}

// ---------------------------------------------------------------- main
__global__ __launch_bounds__(TPB, 3)
void vq_main(const float* __restrict__ x, const float* __restrict__ emb,
             float* __restrict__ out, int out_size) {
    extern __shared__ __align__(16) char sm[];
    float*  sRE   = (float*)(sm + SM_RE);    // ||e||^2 * 2^20
    float*  sRX   = (float*)(sm + SM_RX);
    int*    sRedI = (int*)  (sm + SM_REDI);  // aliases B buffers (post-loop only)
    double* sLoss = (double*)(sm + SM_LOSS);
    float*  sRed2 = (float*)(sm + SM_RED2);
    unsigned int* sFlag = (unsigned int*)(sm + SM_FLAG);

    const uint32_t smb = smem_u32(sm);
    const int tid = threadIdx.x, wid = tid >> 5, l = tid & 31;
    const int wm = wid & 3, wn = wid >> 2;          // 4 x 2 warp grid
    const size_t row0 = (size_t)blockIdx.x * RPB;

    // ---- prefetch B chunks 0,1 (double-buffered) ----
#pragma unroll
    for (int c = 0; c < 2; ++c) {
        uint32_t dst = smb + SM_B + c * B_CH;
        const unsigned char* src = g_eT + (size_t)c * B_CH;
        for (int i = tid; i < B_CH / 16; i += TPB)
            cp_async16(dst + i * 16, src + i * 16);
        CP_COMMIT();
    }

    // ---- stage x (bf16, padded) + fp64 row norms ----
    {
        int row = tid >> 1, half = tid & 1;
        const float4* xr = (const float4*)(x + (row0 + row) * DIMV + half * 64);
        char* base = sm + SM_XA + row * ROWB + half * 128;
        double s = 0.0;
#pragma unroll
        for (int i = 0; i < 16; ++i) {
            float4 v = xr[i];
            s += (double)__fmul_rn(v.x, v.x) + (double)__fmul_rn(v.y, v.y)
               + (double)__fmul_rn(v.z, v.z) + (double)__fmul_rn(v.w, v.w);
            *(__nv_bfloat162*)(base + i * 8)     =
                __halves2bfloat162(__float2bfloat16_rn(v.x), __float2bfloat16_rn(v.y));
            *(__nv_bfloat162*)(base + i * 8 + 4) =
                __halves2bfloat162(__float2bfloat16_rn(v.z), __float2bfloat16_rn(v.w));
        }
        s += __shfl_xor_sync(0xffffffffu, s, 1);
        if (!half) sRX[row] = (float)s;
    }
    for (int i = tid; i < KCODES; i += TPB) sRE[i] = g_re[i];
    __syncthreads();   // staging of A/rx visible

    uint32_t aAddr[2];
#pragma unroll
    for (int mi = 0; mi < 2; ++mi)
        aAddr[mi] = smb + SM_XA
                  + (wm * 32 + mi * 16 + (l & 15)) * ROWB + ((l >> 4) & 1) * 16;
    uint32_t bOff[2];
#pragma unroll
    for (int g = 0; g < 2; ++g)
        bOff[g] = (wn * 32 + g * 16 + (l & 7) + ((l >> 4) & 1) * 8) * ROWB
                + ((l >> 3) & 1) * 16;

    // per-slot top-2 integer keys (4 row-slots per thread)
    int kb[4], ks[4];
#pragma unroll
    for (int s = 0; s < 4; ++s) { kb[s] = ks[s] = 0x7fffffff; }

#pragma unroll 1
    for (int c = 0; c < NCH; ++c) {
        if (c + 1 < NCH) CP_WAIT1(); else CP_WAIT0();
        __syncthreads();                 // buf (c&1) ready for all
        uint32_t bB = smb + SM_B + (c & 1) * B_CH;

        float acc[2][4][4];
#pragma unroll
        for (int mi = 0; mi < 2; ++mi)
#pragma unroll
            for (int ni = 0; ni < 4; ++ni)
#pragma unroll
                for (int q = 0; q < 4; ++q) acc[mi][ni][q] = 0.f;

#pragma unroll
        for (int ksx = 0; ksx < 8; ++ksx) {
            uint32_t A[2][4], B[2][4];
            LDSM4(A[0], aAddr[0] + ksx * 32);
            LDSM4(A[1], aAddr[1] + ksx * 32);
            LDSM4(B[0], bB + bOff[0] + ksx * 32);
            LDSM4(B[1], bB + bOff[1] + ksx * 32);
#pragma unroll
            for (int mi = 0; mi < 2; ++mi)
#pragma unroll
                for (int ni = 0; ni < 4; ++ni)
                    MMA16816(acc[mi][ni], A[mi],
                             B[ni >> 1][(ni & 1) * 2], B[ni >> 1][(ni & 1) * 2 + 1]);
        }

        // epilogue: int-key selection, key = rn((re-2m)*2^20)*1024 + code
        int cb = c * CPC + wn * 32;
#pragma unroll
        for (int ni = 0; ni < 4; ++ni) {
            int code0 = cb + ni * 8 + 2 * (l & 3);
            float re0 = sRE[code0], re1 = sRE[code0 + 1];
#pragma unroll
            for (int mi = 0; mi < 2; ++mi) {
                int s0 = mi * 2, s1 = mi * 2 + 1;
                int key;
                key = __float2int_rn(__fmaf_rn(acc[mi][ni][0], KM2, re0)) * 1024 + code0;
                INSK(key, kb[s0], ks[s0]);
                key = __float2int_rn(__fmaf_rn(acc[mi][ni][1], KM2, re1)) * 1024 + code0 + 1;
                INSK(key, kb[s0], ks[s0]);
                key = __float2int_rn(__fmaf_rn(acc[mi][ni][2], KM2, re0)) * 1024 + code0;
                INSK(key, kb[s1], ks[s1]);
                key = __float2int_rn(__fmaf_rn(acc[mi][ni][3], KM2, re1)) * 1024 + code0 + 1;
                INSK(key, kb[s1], ks[s1]);
            }
        }
        __syncthreads();                 // readers done with buf (c&1)
        if (c + 2 < NCH) {               // prefetch chunk c+2 into freed buffer
            uint32_t dst = smb + SM_B + (c & 1) * B_CH;
            const unsigned char* src = g_eT + (size_t)(c + 2) * B_CH;
            for (int i = tid; i < B_CH / 16; i += TPB)
                cp_async16(dst + i * 16, src + i * 16);
            CP_COMMIT();
        }
    }

    // ---- one xor-2 merge (integer), then dump 8 candidate keys per row ----
    // NOTE: sRedI aliases the B buffers; all B reads are ordered before these
    // writes by the final in-loop __syncthreads.
#pragma unroll
    for (int s = 0; s < 4; ++s) {
        int ob = __shfl_xor_sync(0xffffffffu, kb[s], 2);
        int os = __shfl_xor_sync(0xffffffffu, ks[s], 2);
        int nb = min(kb[s], ob);
        int mx = max(kb[s], ob);
        ks[s] = min(min(ks[s], os), mx);
        kb[s] = nb;
    }
    if ((l & 3) < 2) {
#pragma unroll
        for (int s = 0; s < 4; ++s) {
            int r = wm * 32 + (l >> 2) + s * 8;
            int base = r * 8 + wn * 4 + (l & 3) * 2;
            sRedI[base]     = kb[s];
            sRedI[base + 1] = ks[s];
        }
    }
    __syncthreads();

    // ---- recheck: 1 warp per row, coalesced, batched MLP-4, EXACT fp32 ----
    {
        const float4* e4 = (const float4*)emb;
#pragma unroll 1
        for (int it = 0; it < 16; ++it) {
            int row = wid * 16 + it;
            float4 xv = ((const float4*)(x + (row0 + row) * DIMV))[l];
            float rx = sRX[row];
            float fD = 3.402823466e38f;
            int   fI = 0x7fffffff;
#pragma unroll
            for (int g = 0; g < 2; ++g) {
                int   cds[4];
                float p[4];
#pragma unroll
                for (int t = 0; t < 4; ++t)
                    cds[t] = sRedI[row * 8 + g * 4 + t] & 1023;
#pragma unroll
                for (int t = 0; t < 4; ++t) {
                    float4 ev = e4[(size_t)cds[t] * 32 + l];
                    p[t] = __fmaf_rn(xv.x, ev.x,
                           __fmaf_rn(xv.y, ev.y,
                           __fmaf_rn(xv.z, ev.z, __fmul_rn(xv.w, ev.w))));
                }
#pragma unroll
                for (int o = 16; o > 0; o >>= 1)
#pragma unroll
                    for (int t = 0; t < 4; ++t)
                        p[t] = __fadd_rn(p[t], __shfl_xor_sync(0xffffffffu, p[t], o));
#pragma unroll
                for (int t = 0; t < 4; ++t) {
                    float re = __fmul_rn(sRE[cds[t]], KUNSCALE);   // exact (pow2)
                    float d  = __fadd_rn(__fadd_rn(rx, re), __fmul_rn(p[t], -2.0f));
                    if (lt(d, cds[t], fD, fI)) { fD = d; fI = cds[t]; }
                }
            }
            if (l == 0) {
                sRedI[row * 8] = fI;     // per-row winner (plain code)
                atomicAdd(&g_counts[fI], 1);
            }
        }
    }
    __syncthreads();

    // ---- fused output: STE-rounded gather + loss partial (fp32 -> fp64) ----
    double ls = 0.0;
    {
        const float4* xin4 = (const float4*)(x + row0 * DIMV);
        float4*       o4   = (float4*)(out + row0 * DIMV);
        const float4* e4   = (const float4*)emb;
        for (int i = tid; i < RPB * (DIMV / 4); i += TPB) {
            int rr  = i >> 5;
            int col = i & 31;
            float4 q  = e4[(size_t)sRedI[rr * 8] * 32 + col];
            float4 xv = xin4[i];
            float4 o;
            o.x = __fadd_rn(xv.x, __fadd_rn(q.x, -xv.x));
            o.y = __fadd_rn(xv.y, __fadd_rn(q.y, -xv.y));
            o.z = __fadd_rn(xv.z, __fadd_rn(q.z, -xv.z));
            o.w = __fadd_rn(xv.w, __fadd_rn(q.w, -xv.w));
            o4[i] = o;
            float dx = q.x - xv.x, dy = q.y - xv.y;
            float dz = q.z - xv.z, dw = q.w - xv.w;
            float f = __fmaf_rn(dx, dx, __fmaf_rn(dy, dy,
                      __fmaf_rn(dz, dz, __fmul_rn(dw, dw))));
            ls += (double)f;
        }
    }
#pragma unroll
    for (int o = 16; o > 0; o >>= 1) ls += __shfl_down_sync(0xffffffffu, ls, o);
    if (l == 0) sLoss[wid] = ls;
    __syncthreads();
    if (tid == 0) {
        double t = 0.0;
#pragma unroll
        for (int i = 0; i < 8; ++i) t += sLoss[i];
        atomicAdd(&g_loss, t);
        __threadfence();
        unsigned int tk = atomicAdd(&g_ticket, 1u);
        sFlag[0] = (tk == (unsigned int)(NBLOCKS - 1)) ? 1u : 0u;
    }
    __syncthreads();

    // ---- fused finalize (last block only): perplexity + loss scalars ----
    if (sFlag[0]) {
        __threadfence();
        float acc = 0.f;
        for (int k = tid; k < KCODES; k += TPB) {
            float p = (float)__ldcg(&g_counts[k]) * (1.0f / (float)N_ROWS);
            acc += p * logf(p + 1e-10f);
        }
#pragma unroll
        for (int o = 16; o > 0; o >>= 1) acc += __shfl_down_sync(0xffffffffu, acc, o);
        if (l == 0) sRed2[wid] = acc;
        __syncthreads();
        if (tid == 0) {
            float s = 0.f;
#pragma unroll
            for (int i = 0; i < 8; ++i) s += sRed2[i];
            double lv = __ldcg(&g_loss);
            out[out_size - 2] = (float)(1.25 * (lv / (double)(N_ROWS * DIMV)));
            out[out_size - 1] = expf(-s);
        }
    }
}

// ----------------------------------------------------------------
extern "C" void kernel_launch(void* const* d_in, const int* in_sizes, int n_in,
                              void* d_out, int out_size) {
    const float* x   = (const float*)d_in[0];
    const float* emb = (const float*)d_in[1];
    float*       out = (float*)d_out;
    (void)in_sizes; (void)n_in;

    cudaFuncSetAttribute(vq_main, cudaFuncAttributeMaxDynamicSharedMemorySize,
                         SMEM_TOTAL);

    vq_prep<<<16, 256>>>(emb);
    vq_main<<<NBLOCKS, TPB, SMEM_TOTAL>>>(x, emb, out, out_size);
}

// round 17
// speedup vs baseline: 4.2170x; 1.0245x over previous
#include <cuda_runtime.h>
#include <cuda_bf16.h>
#include <cstdint>

// ---------------------------------------------------------------- constants
#define N_ROWS   65536
#define DIMV     128
#define KCODES   1024
#define RPB      128                  // rows per block (M)
#define CPC      64                   // codes per chunk (N)
#define NCH      (KCODES / CPC)       // 16
#define TPB      256
#define NBLOCKS  (N_ROWS / RPB)       // 512

// padded bf16 row: 136 elems = 272 B = 17 x 16B granules (conflict-free ldmatrix)
#define ROWB     272
#define XA_B     (RPB * ROWB)         // 34816
#define B_CH     (CPC * ROWB)         // 17408 per chunk
#define ETB      (KCODES * ROWB)      // 278528

// smem layout (total 56944 -> 4 blocks/SM, single wave)
#define SM_XA    0
#define SM_B     XA_B                         // 34816 (SINGLE buffer)
#define SM_RE    (SM_B + B_CH)                // 52224 (stores ||e||^2 * 2^20)
#define SM_RX    (SM_RE + KCODES * 4)         // 56320
#define SM_LOSS  (SM_RX + RPB * 4)            // 56832
#define SM_RED2  (SM_LOSS + 64)               // 56896
#define SM_FLAG  (SM_RED2 + 32)               // 56928
#define SM_REDI  SM_B                         // ALIAS: candidates written after
                                              // all B reads complete (sync-ordered)
#define SMEM_TOTAL (SM_FLAG + 16)             // 56944

#define KSCALE   1048576.0f            // 2^20
#define KUNSCALE 9.5367431640625e-7f   // 2^-20 (exact)
#define KM2      -2097152.0f           // -2 * 2^20

// ---------------------------------------------------------------- scratch
__device__ float        g_re[KCODES];   // ||e||^2 * 2^20
__device__ int          g_counts[KCODES];
__device__ double       g_loss;
__device__ unsigned int g_ticket;
// bf16 codebook (rounded), padded rows: [1024][136] bf16
__device__ __align__(16) unsigned char g_eT[ETB];

// ---------------------------------------------------------------- helpers
__device__ __forceinline__ uint32_t smem_u32(const void* p) {
    uint32_t a;
    asm("{ .reg .u64 t; cvta.to.shared.u64 t, %1; cvt.u32.u64 %0, t; }"
        : "=r"(a) : "l"(p));
    return a;
}
static __device__ __forceinline__ void cp_async16(uint32_t dst, const void* src) {
    asm volatile("cp.async.cg.shared.global [%0], [%1], 16;\n" :: "r"(dst), "l"(src));
}
#define CP_COMMIT() asm volatile("cp.async.commit_group;\n" ::: "memory")
#define CP_WAIT0()  asm volatile("cp.async.wait_group 0;\n" ::: "memory")

#define LDSM4(r, addr) \
    asm volatile("ldmatrix.sync.aligned.m8n8.x4.shared.b16 {%0,%1,%2,%3}, [%4];" \
        : "=r"((r)[0]), "=r"((r)[1]), "=r"((r)[2]), "=r"((r)[3]) : "r"(addr))

#define MMA16816(c, a, b0, b1) \
    asm volatile("mma.sync.aligned.m16n8k16.row.col.f32.bf16.bf16.f32 " \
        "{%0,%1,%2,%3}, {%4,%5,%6,%7}, {%8,%9}, {%0,%1,%2,%3};" \
        : "+f"((c)[0]), "+f"((c)[1]), "+f"((c)[2]), "+f"((c)[3]) \
        : "r"((a)[0]), "r"((a)[1]), "r"((a)[2]), "r"((a)[3]), "r"(b0), "r"(b1))

// ordering with index tie-break (exact recheck only)
static __device__ __forceinline__ bool lt(float dA, int iA, float dB, int iB) {
    return dA < dB || (dA == dB && iA < iB);
}
// integer top-2 insert: 3 IMNMX, no predicates
#define INSK(key, kb, ks) do {                         \
    int _mn = min((key), (kb)), _mx = max((key), (kb)); \
    (kb) = _mn; (ks) = min((ks), _mx);                  \
} while (0)

// ---------------------------------------------------------------- prep
// 4 threads per code: ||e||^2 (fp32 squares, fp64 sum -> fp32, *2^20) + bf16 tile.
__global__ void vq_prep(const float* __restrict__ emb) {
    int g = blockIdx.x * blockDim.x + threadIdx.x;   // 0..4095
    int k = g >> 2, q = g & 3;
    const float4* e4 = (const float4*)(emb + (size_t)k * DIMV + q * 32);
    unsigned char* base = g_eT + (size_t)k * ROWB + q * 64;
    double s = 0.0;
#pragma unroll
    for (int i = 0; i < 8; ++i) {
        float4 v = e4[i];
        s += (double)__fmul_rn(v.x, v.x) + (double)__fmul_rn(v.y, v.y)
           + (double)__fmul_rn(v.z, v.z) + (double)__fmul_rn(v.w, v.w);
        *(__nv_bfloat162*)(base + i * 8)     =
            __halves2bfloat162(__float2bfloat16_rn(v.x), __float2bfloat16_rn(v.y));
        *(__nv_bfloat162*)(base + i * 8 + 4) =
            __halves2bfloat162(__float2bfloat16_rn(v.z), __float2bfloat16_rn(v.w));
    }
    s += __shfl_xor_sync(0xffffffffu, s, 1);
    s += __shfl_xor_sync(0xffffffffu, s, 2);
    if (q == 0) { g_re[k] = (float)s * KSCALE; g_counts[k] = 0; }
    if (g == 0) { g_loss = 0.0; g_ticket = 0u; }
}

// ---------------------------------------------------------------- main
__global__ __launch_bounds__(TPB, 4)
void vq_main(const float* __restrict__ x, const float* __restrict__ emb,
             float* __restrict__ out, int out_size) {
    extern __shared__ __align__(16) char sm[];
    float*  sRE   = (float*)(sm + SM_RE);    // ||e||^2 * 2^20
    float*  sRX   = (float*)(sm + SM_RX);
    int*    sRedI = (int*)  (sm + SM_REDI);  // aliases B buffer (post-loop only)
    double* sLoss = (double*)(sm + SM_LOSS);
    float*  sRed2 = (float*)(sm + SM_RED2);
    unsigned int* sFlag = (unsigned int*)(sm + SM_FLAG);

    const uint32_t smb = smem_u32(sm);
    const int tid = threadIdx.x, wid = tid >> 5, l = tid & 31;
    const int wm = wid & 3, wn = wid >> 2;          // 4 x 2 warp grid
    const size_t row0 = (size_t)blockIdx.x * RPB;

    // ---- prefetch B chunk 0 into the single buffer ----
    {
        uint32_t dst = smb + SM_B;
        const unsigned char* src = g_eT;
        for (int i = tid; i < B_CH / 16; i += TPB)
            cp_async16(dst + i * 16, src + i * 16);
        CP_COMMIT();
    }

    // ---- stage x (bf16, padded) + fp64 row norms ----
    {
        int row = tid >> 1, half = tid & 1;
        const float4* xr = (const float4*)(x + (row0 + row) * DIMV + half * 64);
        char* base = sm + SM_XA + row * ROWB + half * 128;
        double s = 0.0;
#pragma unroll
        for (int i = 0; i < 16; ++i) {
            float4 v = xr[i];
            s += (double)__fmul_rn(v.x, v.x) + (double)__fmul_rn(v.y, v.y)
               + (double)__fmul_rn(v.z, v.z) + (double)__fmul_rn(v.w, v.w);
            *(__nv_bfloat162*)(base + i * 8)     =
                __halves2bfloat162(__float2bfloat16_rn(v.x), __float2bfloat16_rn(v.y));
            *(__nv_bfloat162*)(base + i * 8 + 4) =
                __halves2bfloat162(__float2bfloat16_rn(v.z), __float2bfloat16_rn(v.w));
        }
        s += __shfl_xor_sync(0xffffffffu, s, 1);
        if (!half) sRX[row] = (float)s;
    }
    for (int i = tid; i < KCODES; i += TPB) sRE[i] = g_re[i];

    uint32_t aAddr[2];
#pragma unroll
    for (int mi = 0; mi < 2; ++mi)
        aAddr[mi] = smb + SM_XA
                  + (wm * 32 + mi * 16 + (l & 15)) * ROWB + ((l >> 4) & 1) * 16;
    uint32_t bOff[2];
#pragma unroll
    for (int g = 0; g < 2; ++g)
        bOff[g] = (wn * 32 + g * 16 + (l & 7) + ((l >> 4) & 1) * 8) * ROWB
                + ((l >> 3) & 1) * 16;

    // per-slot top-2 integer keys (4 row-slots per thread)
    int kb[4], ks[4];
#pragma unroll
    for (int s = 0; s < 4; ++s) { kb[s] = ks[s] = 0x7fffffff; }

#pragma unroll 1
    for (int c = 0; c < NCH; ++c) {
        CP_WAIT0();
        __syncthreads();                 // B chunk c (and staging, c==0) visible
        uint32_t bB = smb + SM_B;

        float acc[2][4][4];
#pragma unroll
        for (int mi = 0; mi < 2; ++mi)
#pragma unroll
            for (int ni = 0; ni < 4; ++ni)
#pragma unroll
                for (int q = 0; q < 4; ++q) acc[mi][ni][q] = 0.f;

#pragma unroll
        for (int ksx = 0; ksx < 8; ++ksx) {
            uint32_t A[2][4], B[2][4];
            LDSM4(A[0], aAddr[0] + ksx * 32);
            LDSM4(A[1], aAddr[1] + ksx * 32);
            LDSM4(B[0], bB + bOff[0] + ksx * 32);
            LDSM4(B[1], bB + bOff[1] + ksx * 32);
#pragma unroll
            for (int mi = 0; mi < 2; ++mi)
#pragma unroll
                for (int ni = 0; ni < 4; ++ni)
                    MMA16816(acc[mi][ni], A[mi],
                             B[ni >> 1][(ni & 1) * 2], B[ni >> 1][(ni & 1) * 2 + 1]);
        }

        // epilogue: int-key selection, key = rn((re-2m)*2^20)*1024 + code
        int cb = c * CPC + wn * 32;
#pragma unroll
        for (int ni = 0; ni < 4; ++ni) {
            int code0 = cb + ni * 8 + 2 * (l & 3);
            float re0 = sRE[code0], re1 = sRE[code0 + 1];
#pragma unroll
            for (int mi = 0; mi < 2; ++mi) {
                int s0 = mi * 2, s1 = mi * 2 + 1;
                int key;
                key = __float2int_rn(__fmaf_rn(acc[mi][ni][0], KM2, re0)) * 1024 + code0;
                INSK(key, kb[s0], ks[s0]);
                key = __float2int_rn(__fmaf_rn(acc[mi][ni][1], KM2, re1)) * 1024 + code0 + 1;
                INSK(key, kb[s0], ks[s0]);
                key = __float2int_rn(__fmaf_rn(acc[mi][ni][2], KM2, re0)) * 1024 + code0;
                INSK(key, kb[s1], ks[s1]);
                key = __float2int_rn(__fmaf_rn(acc[mi][ni][3], KM2, re1)) * 1024 + code0 + 1;
                INSK(key, kb[s1], ks[s1]);
            }
        }
        __syncthreads();                 // all readers done with the buffer
        if (c + 1 < NCH) {               // load next chunk into the SAME buffer
            uint32_t dst = smb + SM_B;
            const unsigned char* src = g_eT + (size_t)(c + 1) * B_CH;
            for (int i = tid; i < B_CH / 16; i += TPB)
                cp_async16(dst + i * 16, src + i * 16);
            CP_COMMIT();
        }
    }

    // ---- one xor-2 merge (integer), then dump 8 candidate keys per row ----
    // NOTE: sRedI aliases the B buffer; all B reads are ordered before these
    // writes by the final in-loop __syncthreads.
#pragma unroll
    for (int s = 0; s < 4; ++s) {
        int ob = __shfl_xor_sync(0xffffffffu, kb[s], 2);
        int os = __shfl_xor_sync(0xffffffffu, ks[s], 2);
        int nb = min(kb[s], ob);
        int mx = max(kb[s], ob);
        ks[s] = min(min(ks[s], os), mx);
        kb[s] = nb;
    }
    if ((l & 3) < 2) {
#pragma unroll
        for (int s = 0; s < 4; ++s) {
            int r = wm * 32 + (l >> 2) + s * 8;
            int base = r * 8 + wn * 4 + (l & 3) * 2;
            sRedI[base]     = kb[s];
            sRedI[base + 1] = ks[s];
        }
    }
    __syncthreads();

    // ---- recheck: 1 warp per row, coalesced, batched MLP-4, EXACT fp32 ----
    {
        const float4* e4 = (const float4*)emb;
#pragma unroll 1
        for (int it = 0; it < 16; ++it) {
            int row = wid * 16 + it;
            float4 xv = ((const float4*)(x + (row0 + row) * DIMV))[l];
            float rx = sRX[row];
            float fD = 3.402823466e38f;
            int   fI = 0x7fffffff;
#pragma unroll
            for (int g = 0; g < 2; ++g) {
                int   cds[4];
                float p[4];
#pragma unroll
                for (int t = 0; t < 4; ++t)
                    cds[t] = sRedI[row * 8 + g * 4 + t] & 1023;
#pragma unroll
                for (int t = 0; t < 4; ++t) {
                    float4 ev = e4[(size_t)cds[t] * 32 + l];
                    p[t] = __fmaf_rn(xv.x, ev.x,
                           __fmaf_rn(xv.y, ev.y,
                           __fmaf_rn(xv.z, ev.z, __fmul_rn(xv.w, ev.w))));
                }
#pragma unroll
                for (int o = 16; o > 0; o >>= 1)
#pragma unroll
                    for (int t = 0; t < 4; ++t)
                        p[t] = __fadd_rn(p[t], __shfl_xor_sync(0xffffffffu, p[t], o));
#pragma unroll
                for (int t = 0; t < 4; ++t) {
                    float re = __fmul_rn(sRE[cds[t]], KUNSCALE);   // exact (pow2)
                    float d  = __fadd_rn(__fadd_rn(rx, re), __fmul_rn(p[t], -2.0f));
                    if (lt(d, cds[t], fD, fI)) { fD = d; fI = cds[t]; }
                }
            }
            if (l == 0) {
                sRedI[row * 8] = fI;     // per-row winner (plain code)
                atomicAdd(&g_counts[fI], 1);
            }
        }
    }
    __syncthreads();

    // ---- fused output: STE-rounded gather + loss partial (fp32 -> fp64) ----
    double ls = 0.0;
    {
        const float4* xin4 = (const float4*)(x + row0 * DIMV);
        float4*       o4   = (float4*)(out + row0 * DIMV);
        const float4* e4   = (const float4*)emb;
        for (int i = tid; i < RPB * (DIMV / 4); i += TPB) {
            int rr  = i >> 5;
            int col = i & 31;
            float4 q  = e4[(size_t)sRedI[rr * 8] * 32 + col];
            float4 xv = xin4[i];
            float4 o;
            o.x = __fadd_rn(xv.x, __fadd_rn(q.x, -xv.x));
            o.y = __fadd_rn(xv.y, __fadd_rn(q.y, -xv.y));
            o.z = __fadd_rn(xv.z, __fadd_rn(q.z, -xv.z));
            o.w = __fadd_rn(xv.w, __fadd_rn(q.w, -xv.w));
            o4[i] = o;
            float dx = q.x - xv.x, dy = q.y - xv.y;
            float dz = q.z - xv.z, dw = q.w - xv.w;
            float f = __fmaf_rn(dx, dx, __fmaf_rn(dy, dy,
                      __fmaf_rn(dz, dz, __fmul_rn(dw, dw))));
            ls += (double)f;
        }
    }
#pragma unroll
    for (int o = 16; o > 0; o >>= 1) ls += __shfl_down_sync(0xffffffffu, ls, o);
    if (l == 0) sLoss[wid] = ls;
    __syncthreads();
    if (tid == 0) {
        double t = 0.0;
#pragma unroll
        for (int i = 0; i < 8; ++i) t += sLoss[i];
        atomicAdd(&g_loss, t);
        __threadfence();
        unsigned int tk = atomicAdd(&g_ticket, 1u);
        sFlag[0] = (tk == (unsigned int)(NBLOCKS - 1)) ? 1u : 0u;
    }
    __syncthreads();

    // ---- fused finalize (last block only): perplexity + loss scalars ----
    if (sFlag[0]) {
        __threadfence();
        float acc = 0.f;
        for (int k = tid; k < KCODES; k += TPB) {
            float p = (float)__ldcg(&g_counts[k]) * (1.0f / (float)N_ROWS);
            acc += p * logf(p + 1e-10f);
        }
#pragma unroll
        for (int o = 16; o > 0; o >>= 1) acc += __shfl_down_sync(0xffffffffu, acc, o);
        if (l == 0) sRed2[wid] = acc;
        __syncthreads();
        if (tid == 0) {
            float s = 0.f;
#pragma unroll
            for (int i = 0; i < 8; ++i) s += sRed2[i];
            double lv = __ldcg(&g_loss);
            out[out_size - 2] = (float)(1.25 * (lv / (double)(N_ROWS * DIMV)));
            out[out_size - 1] = expf(-s);
        }
    }
}

// ----------------------------------------------------------------
extern "C" void kernel_launch(void* const* d_in, const int* in_sizes, int n_in,
                              void* d_out, int out_size) {
    const float* x   = (const float*)d_in[0];
    const float* emb = (const float*)d_in[1];
    float*       out = (float*)d_out;
    (void)in_sizes; (void)n_in;

    cudaFuncSetAttribute(vq_main, cudaFuncAttributeMaxDynamicSharedMemorySize,
                         SMEM_TOTAL);

    vq_prep<<<16, 256>>>(emb);
    vq_main<<<NBLOCKS, TPB, SMEM_TOTAL>>>(x, emb, out, out_size);
}